// round 1
// baseline (speedup 1.0000x reference)
#include <cuda_runtime.h>
#include <math.h>

// Problem constants (fixed per metadata)
#define BATCH  4
#define SEQ    2048
#define C_DIM  1024
#define H_DIM  16
#define D_DIM  64
#define M_DIM  (BATCH * SEQ)          // 8192
#define SCALE  0.125f                 // D^-0.5

// ---------------------------------------------------------------------------
// Device scratch (static __device__ arrays; no allocation anywhere)
// ---------------------------------------------------------------------------
__device__ float g_vw[C_DIM * C_DIM];
__device__ float g_pw[C_DIM * C_DIM];
__device__ float g_pb[C_DIM];
__device__ float g_q [M_DIM * C_DIM];
__device__ float g_k [M_DIM * C_DIM];
__device__ float g_v [M_DIM * C_DIM];
__device__ float g_o [M_DIM * C_DIM];

// ---------------------------------------------------------------------------
// Bayes reparameterization: w = mu + softplus(rho) * eps
// ---------------------------------------------------------------------------
__global__ void bayes_kernel(const float* __restrict__ mu,
                             const float* __restrict__ rho,
                             const float* __restrict__ eps,
                             float* __restrict__ w, int n)
{
    int i = blockIdx.x * 256 + threadIdx.x;
    if (i < n) {
        float r  = rho[i];
        float sp = (r > 15.0f) ? r : log1pf(__expf(r));
        w[i] = fmaf(sp, eps[i], mu[i]);
    }
}

// ---------------------------------------------------------------------------
// SGEMM (NT): Cmat[m,n] = sum_k A[m,k] * B[n,k]  (+ optional bias[n])
// A: [M,K] row-major, B: [N,K] row-major (both K-contiguous).
// Tiles: 128x128x16, 256 threads, 8x8 microtile as 2x2 of float4.
// ---------------------------------------------------------------------------
#define GBM 128
#define GBN 128
#define GBK 16
#define APAD 4

__global__ __launch_bounds__(256, 2)
void sgemm_nt(const float* __restrict__ A, const float* __restrict__ B,
              const float* __restrict__ bias, float* __restrict__ Cmat,
              int Mdim, int Ndim, int Kdim)
{
    __shared__ float As[GBK][GBM + APAD];
    __shared__ float Bs[GBK][GBN + APAD];

    const int tid = threadIdx.x;
    const int tx  = tid & 15;
    const int ty  = tid >> 4;
    const int m0  = blockIdx.y * GBM;
    const int n0  = blockIdx.x * GBN;

    float acc[8][8];
#pragma unroll
    for (int i = 0; i < 8; i++)
#pragma unroll
        for (int j = 0; j < 8; j++) acc[i][j] = 0.0f;

    for (int k0 = 0; k0 < Kdim; k0 += GBK) {
        // Load A/B tiles: 128x16 floats each = 512 float4 each; 2 per thread.
#pragma unroll
        for (int t = 0; t < 2; t++) {
            int f   = tid + t * 256;       // 0..511
            int row = f >> 2;              // 0..127
            int kq  = (f & 3) * 4;         // 0,4,8,12
            float4 va = *(const float4*)(A + (size_t)(m0 + row) * Kdim + k0 + kq);
            As[kq + 0][row] = va.x; As[kq + 1][row] = va.y;
            As[kq + 2][row] = va.z; As[kq + 3][row] = va.w;
            float4 vb = *(const float4*)(B + (size_t)(n0 + row) * Kdim + k0 + kq);
            Bs[kq + 0][row] = vb.x; Bs[kq + 1][row] = vb.y;
            Bs[kq + 2][row] = vb.z; Bs[kq + 3][row] = vb.w;
        }
        __syncthreads();

#pragma unroll
        for (int kk = 0; kk < GBK; kk++) {
            float a[8], b[8];
            *(float4*)(a)     = *(const float4*)&As[kk][ty * 4];
            *(float4*)(a + 4) = *(const float4*)&As[kk][64 + ty * 4];
            *(float4*)(b)     = *(const float4*)&Bs[kk][tx * 4];
            *(float4*)(b + 4) = *(const float4*)&Bs[kk][64 + tx * 4];
#pragma unroll
            for (int i = 0; i < 8; i++)
#pragma unroll
                for (int j = 0; j < 8; j++)
                    acc[i][j] = fmaf(a[i], b[j], acc[i][j]);
        }
        __syncthreads();
    }

    // Epilogue
#pragma unroll
    for (int ib = 0; ib < 2; ib++) {
#pragma unroll
        for (int i = 0; i < 4; i++) {
            int row = m0 + ib * 64 + ty * 4 + i;
#pragma unroll
            for (int jb = 0; jb < 2; jb++) {
                int col = n0 + jb * 64 + tx * 4;
                float4 r;
                r.x = acc[ib * 4 + i][jb * 4 + 0];
                r.y = acc[ib * 4 + i][jb * 4 + 1];
                r.z = acc[ib * 4 + i][jb * 4 + 2];
                r.w = acc[ib * 4 + i][jb * 4 + 3];
                if (bias) {
                    r.x += bias[col + 0]; r.y += bias[col + 1];
                    r.z += bias[col + 2]; r.w += bias[col + 3];
                }
                *(float4*)(Cmat + (size_t)row * Ndim + col) = r;
            }
        }
    }
}

// ---------------------------------------------------------------------------
// Fused flash attention: per (b,h), online-softmax over K/V tiles.
// BQ = BK = 64, D = 64, 256 threads (16x16), 4x4 per thread.
// ---------------------------------------------------------------------------
#define FBQ  64
#define FBK  64
#define FSTR 68  // 64 + 4 pad, keeps float4 alignment (68*4 % 16 == 0)
#define FLASH_SMEM (4 * 64 * FSTR * 4)

__global__ __launch_bounds__(256, 2)
void flash_kernel(const float* __restrict__ Q, const float* __restrict__ K,
                  const float* __restrict__ V, float* __restrict__ O)
{
    extern __shared__ float sm[];
    float* Qs = sm;
    float* Ks = sm + 1 * 64 * FSTR;
    float* Vs = sm + 2 * 64 * FSTR;
    float* Ps = sm + 3 * 64 * FSTR;

    const int tid = threadIdx.x;
    const int tx  = tid & 15;
    const int ty  = tid >> 4;
    const int bh  = blockIdx.y;           // 0..63
    const int b   = bh >> 4;
    const int h   = bh & 15;
    const int q0  = blockIdx.x * FBQ;

    const size_t baseQ  = ((size_t)b * SEQ + q0) * C_DIM + h * D_DIM;
    const size_t baseKV = ((size_t)b * SEQ) * C_DIM + h * D_DIM;

    // Load Q tile: 64 rows x 64 d = 1024 float4; 4 per thread.
#pragma unroll
    for (int t = 0; t < 4; t++) {
        int f   = tid + t * 256;
        int row = f >> 4;
        int dq  = (f & 15) * 4;
        *(float4*)&Qs[row * FSTR + dq] =
            *(const float4*)(Q + baseQ + (size_t)row * C_DIM + dq);
    }

    float m[4], l[4], o[4][4];
#pragma unroll
    for (int i = 0; i < 4; i++) {
        m[i] = -1e30f; l[i] = 0.0f;
#pragma unroll
        for (int j = 0; j < 4; j++) o[i][j] = 0.0f;
    }

    for (int kt = 0; kt < SEQ; kt += FBK) {
        __syncthreads();  // prior-iter consumers done before overwriting Ks/Vs
#pragma unroll
        for (int t = 0; t < 4; t++) {
            int f   = tid + t * 256;
            int row = f >> 4;
            int dq  = (f & 15) * 4;
            *(float4*)&Ks[row * FSTR + dq] =
                *(const float4*)(K + baseKV + (size_t)(kt + row) * C_DIM + dq);
            *(float4*)&Vs[row * FSTR + dq] =
                *(const float4*)(V + baseKV + (size_t)(kt + row) * C_DIM + dq);
        }
        __syncthreads();

        // S tile: s[i][j] = Q[ty*4+i,:] . K[tx*4+j,:]
        float s[4][4];
#pragma unroll
        for (int i = 0; i < 4; i++)
#pragma unroll
            for (int j = 0; j < 4; j++) s[i][j] = 0.0f;

#pragma unroll 4
        for (int d4 = 0; d4 < 16; d4++) {
            float4 qv[4], kv[4];
#pragma unroll
            for (int i = 0; i < 4; i++)
                qv[i] = *(const float4*)&Qs[(ty * 4 + i) * FSTR + d4 * 4];
#pragma unroll
            for (int j = 0; j < 4; j++)
                kv[j] = *(const float4*)&Ks[(tx * 4 + j) * FSTR + d4 * 4];
#pragma unroll
            for (int i = 0; i < 4; i++)
#pragma unroll
                for (int j = 0; j < 4; j++) {
                    s[i][j] = fmaf(qv[i].x, kv[j].x, s[i][j]);
                    s[i][j] = fmaf(qv[i].y, kv[j].y, s[i][j]);
                    s[i][j] = fmaf(qv[i].z, kv[j].z, s[i][j]);
                    s[i][j] = fmaf(qv[i].w, kv[j].w, s[i][j]);
                }
        }

        // Online softmax per row (rows owned by lanes sharing ty; reduce over
        // the 16 tx lanes, which stay within a half-warp -> xor 1,2,4,8).
#pragma unroll
        for (int i = 0; i < 4; i++) {
            float mx = -1e30f;
#pragma unroll
            for (int j = 0; j < 4; j++) {
                s[i][j] *= SCALE;
                mx = fmaxf(mx, s[i][j]);
            }
#pragma unroll
            for (int off = 1; off < 16; off <<= 1)
                mx = fmaxf(mx, __shfl_xor_sync(0xffffffffu, mx, off));
            float mnew = fmaxf(m[i], mx);
            float corr = __expf(m[i] - mnew);
            float rs = 0.0f;
#pragma unroll
            for (int j = 0; j < 4; j++) {
                s[i][j] = __expf(s[i][j] - mnew);
                rs += s[i][j];
            }
#pragma unroll
            for (int off = 1; off < 16; off <<= 1)
                rs += __shfl_xor_sync(0xffffffffu, rs, off);
            l[i] = l[i] * corr + rs;
            m[i] = mnew;
#pragma unroll
            for (int j = 0; j < 4; j++) o[i][j] *= corr;
        }

        // Stage P through smem for the PV product.
#pragma unroll
        for (int i = 0; i < 4; i++) {
            float4 pv;
            pv.x = s[i][0]; pv.y = s[i][1]; pv.z = s[i][2]; pv.w = s[i][3];
            *(float4*)&Ps[(ty * 4 + i) * FSTR + tx * 4] = pv;
        }
        __syncthreads();

        // O += P @ V  (o rows ty*4+i, cols tx*4..tx*4+3)
#pragma unroll 4
        for (int k4 = 0; k4 < 16; k4++) {
            float4 pv[4];
#pragma unroll
            for (int i = 0; i < 4; i++)
                pv[i] = *(const float4*)&Ps[(ty * 4 + i) * FSTR + k4 * 4];
#pragma unroll
            for (int c = 0; c < 4; c++) {
                float4 vv = *(const float4*)&Vs[(k4 * 4 + c) * FSTR + tx * 4];
                float pc[4] = { (&pv[0].x)[c], (&pv[1].x)[c],
                                (&pv[2].x)[c], (&pv[3].x)[c] };
#pragma unroll
                for (int i = 0; i < 4; i++) {
                    o[i][0] = fmaf(pc[i], vv.x, o[i][0]);
                    o[i][1] = fmaf(pc[i], vv.y, o[i][1]);
                    o[i][2] = fmaf(pc[i], vv.z, o[i][2]);
                    o[i][3] = fmaf(pc[i], vv.w, o[i][3]);
                }
            }
        }
    }

    // Normalize and write out.
#pragma unroll
    for (int i = 0; i < 4; i++) {
        float inv = 1.0f / l[i];
        float4 r;
        r.x = o[i][0] * inv; r.y = o[i][1] * inv;
        r.z = o[i][2] * inv; r.w = o[i][3] * inv;
        *(float4*)(O + baseQ + (size_t)(ty * 4 + i) * C_DIM + tx * 4) = r;
    }
}

// ---------------------------------------------------------------------------
// Launch
// ---------------------------------------------------------------------------
extern "C" void kernel_launch(void* const* d_in, const int* in_sizes, int n_in,
                              void* d_out, int out_size)
{
    const float* x     = (const float*)d_in[0];
    const float* q_w   = (const float*)d_in[1];
    const float* k_w   = (const float*)d_in[2];
    const float* v_mu  = (const float*)d_in[3];
    const float* v_rho = (const float*)d_in[4];
    const float* v_eps = (const float*)d_in[5];
    const float* p_mu  = (const float*)d_in[6];
    const float* p_rho = (const float*)d_in[7];
    const float* p_eps = (const float*)d_in[8];
    const float* pb_mu = (const float*)d_in[9];
    const float* pb_rho= (const float*)d_in[10];
    const float* pb_eps= (const float*)d_in[11];
    float* out = (float*)d_out;

    float *vw, *pw, *pb, *q, *k, *v, *o;
    cudaGetSymbolAddress((void**)&vw, g_vw);
    cudaGetSymbolAddress((void**)&pw, g_pw);
    cudaGetSymbolAddress((void**)&pb, g_pb);
    cudaGetSymbolAddress((void**)&q,  g_q);
    cudaGetSymbolAddress((void**)&k,  g_k);
    cudaGetSymbolAddress((void**)&v,  g_v);
    cudaGetSymbolAddress((void**)&o,  g_o);

    cudaFuncSetAttribute(flash_kernel,
                         cudaFuncAttributeMaxDynamicSharedMemorySize, FLASH_SMEM);

    const int nw = C_DIM * C_DIM;
    bayes_kernel<<<(nw + 255) / 256, 256>>>(v_mu, v_rho, v_eps, vw, nw);
    bayes_kernel<<<(nw + 255) / 256, 256>>>(p_mu, p_rho, p_eps, pw, nw);
    bayes_kernel<<<(C_DIM + 255) / 256, 256>>>(pb_mu, pb_rho, pb_eps, pb, C_DIM);

    dim3 ggrid(C_DIM / GBN, M_DIM / GBM);
    sgemm_nt<<<ggrid, 256>>>(x, q_w, nullptr, q, M_DIM, C_DIM, C_DIM);
    sgemm_nt<<<ggrid, 256>>>(x, k_w, nullptr, k, M_DIM, C_DIM, C_DIM);
    sgemm_nt<<<ggrid, 256>>>(x, vw,  nullptr, v, M_DIM, C_DIM, C_DIM);

    flash_kernel<<<dim3(SEQ / FBQ, BATCH * H_DIM), 256, FLASH_SMEM>>>(q, k, v, o);

    sgemm_nt<<<ggrid, 256>>>(o, pw, pb, out, M_DIM, C_DIM, C_DIM);
}

// round 2
// speedup vs baseline: 3.2274x; 3.2274x over previous
#include <cuda_runtime.h>
#include <math.h>
#include <stdint.h>

// Problem constants
#define BATCH  4
#define SEQ    2048
#define C_DIM  1024
#define H_DIM  16
#define D_DIM  64
#define M_DIM  (BATCH * SEQ)          // 8192
#define SCALE  0.125f                 // D^-0.5

// ---------------------------------------------------------------------------
// Device scratch
// ---------------------------------------------------------------------------
__device__ float g_vw[C_DIM * C_DIM];
__device__ float g_pw[C_DIM * C_DIM];
__device__ float g_pb[C_DIM];
__device__ float g_q [M_DIM * C_DIM];
__device__ float g_k [M_DIM * C_DIM];
__device__ float g_v [M_DIM * C_DIM];
__device__ float g_o [M_DIM * C_DIM];

// ---------------------------------------------------------------------------
// Helpers: tf32 rounding + mma
// ---------------------------------------------------------------------------
__device__ __forceinline__ float f2tf(float x) {
    uint32_t u;
    asm("cvt.rna.tf32.f32 %0, %1;" : "=r"(u) : "f"(x));
    return __uint_as_float(u);
}
__device__ __forceinline__ float4 f2tf4(float4 v) {
    v.x = f2tf(v.x); v.y = f2tf(v.y); v.z = f2tf(v.z); v.w = f2tf(v.w);
    return v;
}
// D += A(16x8) @ B(8x8); a,b regs hold tf32 bit patterns.
__device__ __forceinline__ void mma_tf32(float* d,
                                         uint32_t a0, uint32_t a1, uint32_t a2, uint32_t a3,
                                         uint32_t b0, uint32_t b1)
{
    asm volatile(
        "mma.sync.aligned.m16n8k8.row.col.f32.tf32.tf32.f32 "
        "{%0,%1,%2,%3}, {%4,%5,%6,%7}, {%8,%9}, {%0,%1,%2,%3};\n"
        : "+f"(d[0]), "+f"(d[1]), "+f"(d[2]), "+f"(d[3])
        : "r"(a0), "r"(a1), "r"(a2), "r"(a3), "r"(b0), "r"(b1));
}

// ---------------------------------------------------------------------------
// Bayes reparameterization
// ---------------------------------------------------------------------------
__global__ void bayes_kernel(const float* __restrict__ mu,
                             const float* __restrict__ rho,
                             const float* __restrict__ eps,
                             float* __restrict__ w, int n)
{
    int i = blockIdx.x * 256 + threadIdx.x;
    if (i < n) {
        float r  = rho[i];
        float sp = (r > 15.0f) ? r : log1pf(__expf(r));
        w[i] = fmaf(sp, eps[i], mu[i]);
    }
}

// ---------------------------------------------------------------------------
// TF32 tensor-core SGEMM (NT): C[m,n] = sum_k A[m,k] * B[n,k] (+ bias[n])
// 128x128x32 tiles, 256 threads = 8 warps (2M x 4N), warp tile 64x32.
// smem rows padded to 36 floats: frag LDS banks = (4g+t)%32, conflict-free.
// ---------------------------------------------------------------------------
#define GBM 128
#define GBN 128
#define GBK 32
#define GSTR 36

__global__ __launch_bounds__(256, 2)
void sgemm_tf32(const float* __restrict__ A, const float* __restrict__ B,
                const float* __restrict__ bias, float* __restrict__ Cmat,
                int Kdim, int Ndim)
{
    __shared__ float As[GBM * GSTR];
    __shared__ float Bs[GBN * GSTR];

    const int tid  = threadIdx.x;
    const int lane = tid & 31;
    const int w    = tid >> 5;
    const int wm   = w >> 2;        // 0..1  -> row offset wm*64
    const int wn   = w & 3;         // 0..3  -> col offset wn*32
    const int g    = lane >> 2;     // 0..7
    const int t    = lane & 3;      // 0..3
    const int m0   = blockIdx.y * GBM;
    const int n0   = blockIdx.x * GBN;

    float acc[4][4][4];
#pragma unroll
    for (int i = 0; i < 4; i++)
#pragma unroll
        for (int j = 0; j < 4; j++)
#pragma unroll
            for (int c = 0; c < 4; c++) acc[i][j][c] = 0.0f;

    const int lrow = tid >> 1;            // 0..127
    const int lseg = (tid & 1) * 4;       // 0 or 4  (two float4 per row per half)

    for (int k0 = 0; k0 < Kdim; k0 += GBK) {
        // Load tiles: 128 rows x 32 k = 1024 float4 per matrix, 4 per thread.
#pragma unroll
        for (int half = 0; half < 2; half++) {
            int seg = lseg + half * (tid & 1 ? -0 : 0); // placeholder no-op
            (void)seg;
        }
        // A: each thread loads rows lrow, segments lseg and lseg+... use 2 iters
#pragma unroll
        for (int it = 0; it < 2; it++) {
            int f   = tid + it * 256;        // 0..511
            int row = f >> 2;                // 0..127
            int sg  = (f & 3) * 4 + ((f >> 9) & 0); // 0,4,8,12
            sg = (f & 3) * 4;
            {
                float4 va = f2tf4(*(const float4*)(A + (size_t)(m0 + row) * Kdim + k0 + sg));
                *(float4*)&As[row * GSTR + sg] = va;
                float4 vb = f2tf4(*(const float4*)(B + (size_t)(n0 + row) * Kdim + k0 + sg));
                *(float4*)&Bs[row * GSTR + sg] = vb;
            }
            // second float4 of the row (k 16..31)
            {
                int sg2 = sg + 16;
                float4 va = f2tf4(*(const float4*)(A + (size_t)(m0 + row) * Kdim + k0 + sg2));
                *(float4*)&As[row * GSTR + sg2] = va;
                float4 vb = f2tf4(*(const float4*)(B + (size_t)(n0 + row) * Kdim + k0 + sg2));
                *(float4*)&Bs[row * GSTR + sg2] = vb;
            }
        }
        __syncthreads();

#pragma unroll
        for (int kk = 0; kk < 4; kk++) {
            const int kb = kk * 8;
            uint32_t af[4][4];
#pragma unroll
            for (int mt = 0; mt < 4; mt++) {
                int rb = wm * 64 + mt * 16;
                af[mt][0] = __float_as_uint(As[(rb + g    ) * GSTR + kb + t    ]);
                af[mt][1] = __float_as_uint(As[(rb + g + 8) * GSTR + kb + t    ]);
                af[mt][2] = __float_as_uint(As[(rb + g    ) * GSTR + kb + t + 4]);
                af[mt][3] = __float_as_uint(As[(rb + g + 8) * GSTR + kb + t + 4]);
            }
            uint32_t bf[4][2];
#pragma unroll
            for (int nt = 0; nt < 4; nt++) {
                int cb = wn * 32 + nt * 8;
                bf[nt][0] = __float_as_uint(Bs[(cb + g) * GSTR + kb + t    ]);
                bf[nt][1] = __float_as_uint(Bs[(cb + g) * GSTR + kb + t + 4]);
            }
#pragma unroll
            for (int mt = 0; mt < 4; mt++)
#pragma unroll
                for (int nt = 0; nt < 4; nt++)
                    mma_tf32(acc[mt][nt], af[mt][0], af[mt][1], af[mt][2], af[mt][3],
                             bf[nt][0], bf[nt][1]);
        }
        __syncthreads();
    }

    // Epilogue
#pragma unroll
    for (int mt = 0; mt < 4; mt++) {
        int r0 = m0 + wm * 64 + mt * 16 + g;
#pragma unroll
        for (int nt = 0; nt < 4; nt++) {
            int c0 = n0 + wn * 32 + nt * 8 + 2 * t;
            float bx = 0.0f, by = 0.0f;
            if (bias) { bx = bias[c0]; by = bias[c0 + 1]; }
            float2 v0 = make_float2(acc[mt][nt][0] + bx, acc[mt][nt][1] + by);
            float2 v1 = make_float2(acc[mt][nt][2] + bx, acc[mt][nt][3] + by);
            *(float2*)(Cmat + (size_t)r0 * Ndim + c0)       = v0;
            *(float2*)(Cmat + (size_t)(r0 + 8) * Ndim + c0) = v1;
        }
    }
}

// ---------------------------------------------------------------------------
// TF32 tensor-core flash attention.
// 128 threads = 4 warps; warp w owns S rows [w*16, w*16+16), all 64 cols.
// BQ = BK = 64, D = 64. Smem rows padded to 68 floats.
// ---------------------------------------------------------------------------
#define FSTR 68
#define FLASH_SMEM (4 * 64 * FSTR * 4)

__global__ __launch_bounds__(128, 3)
void flash_tf32(const float* __restrict__ Q, const float* __restrict__ K,
                const float* __restrict__ V, float* __restrict__ O)
{
    extern __shared__ float sm[];
    float* Qs = sm;
    float* Ks = sm + 1 * 64 * FSTR;
    float* Vs = sm + 2 * 64 * FSTR;
    float* Ps = sm + 3 * 64 * FSTR;

    const int tid  = threadIdx.x;
    const int lane = tid & 31;
    const int w    = tid >> 5;      // 0..3
    const int g    = lane >> 2;     // 0..7
    const int t    = lane & 3;      // 0..3
    const int rb   = w * 16;        // warp's S-row base
    const int bh   = blockIdx.y;
    const int b    = bh >> 4;
    const int h    = bh & 15;
    const int q0   = blockIdx.x * 64;

    const size_t baseQ  = ((size_t)b * SEQ + q0) * C_DIM + h * D_DIM;
    const size_t baseKV = ((size_t)b * SEQ) * C_DIM + h * D_DIM;

    // Load Q tile: 64x64 = 1024 float4, 8 per thread.
#pragma unroll
    for (int it = 0; it < 8; it++) {
        int f   = tid + it * 128;
        int row = f >> 4;
        int dq  = (f & 15) * 4;
        *(float4*)&Qs[row * FSTR + dq] =
            f2tf4(*(const float4*)(Q + baseQ + (size_t)row * C_DIM + dq));
    }

    // Per-thread state: two row-halves (g and g+8 within warp band).
    float m0 = -1e30f, m1 = -1e30f, l0 = 0.0f, l1 = 0.0f;
    float oacc[8][4];
#pragma unroll
    for (int nt = 0; nt < 8; nt++)
#pragma unroll
        for (int c = 0; c < 4; c++) oacc[nt][c] = 0.0f;

    for (int kt = 0; kt < SEQ; kt += 64) {
        __syncthreads();
#pragma unroll
        for (int it = 0; it < 8; it++) {
            int f   = tid + it * 128;
            int row = f >> 4;
            int dq  = (f & 15) * 4;
            *(float4*)&Ks[row * FSTR + dq] =
                f2tf4(*(const float4*)(K + baseKV + (size_t)(kt + row) * C_DIM + dq));
            *(float4*)&Vs[row * FSTR + dq] =
                f2tf4(*(const float4*)(V + baseKV + (size_t)(kt + row) * C_DIM + dq));
        }
        __syncthreads();

        // ---- S = Q @ K^T ----
        float s[8][4];
#pragma unroll
        for (int nt = 0; nt < 8; nt++)
#pragma unroll
            for (int c = 0; c < 4; c++) s[nt][c] = 0.0f;

#pragma unroll
        for (int kk = 0; kk < 8; kk++) {
            const int kb = kk * 8;
            uint32_t a0 = __float_as_uint(Qs[(rb + g    ) * FSTR + kb + t    ]);
            uint32_t a1 = __float_as_uint(Qs[(rb + g + 8) * FSTR + kb + t    ]);
            uint32_t a2 = __float_as_uint(Qs[(rb + g    ) * FSTR + kb + t + 4]);
            uint32_t a3 = __float_as_uint(Qs[(rb + g + 8) * FSTR + kb + t + 4]);
#pragma unroll
            for (int nt = 0; nt < 8; nt++) {
                uint32_t b0 = __float_as_uint(Ks[(nt * 8 + g) * FSTR + kb + t    ]);
                uint32_t b1 = __float_as_uint(Ks[(nt * 8 + g) * FSTR + kb + t + 4]);
                mma_tf32(s[nt], a0, a1, a2, a3, b0, b1);
            }
        }

        // ---- online softmax (rows g / g+8; reduce over 4 t-lanes) ----
        float mx0 = -1e30f, mx1 = -1e30f;
#pragma unroll
        for (int nt = 0; nt < 8; nt++) {
            s[nt][0] *= SCALE; s[nt][1] *= SCALE;
            s[nt][2] *= SCALE; s[nt][3] *= SCALE;
            mx0 = fmaxf(mx0, fmaxf(s[nt][0], s[nt][1]));
            mx1 = fmaxf(mx1, fmaxf(s[nt][2], s[nt][3]));
        }
#pragma unroll
        for (int off = 1; off < 4; off <<= 1) {
            mx0 = fmaxf(mx0, __shfl_xor_sync(0xffffffffu, mx0, off));
            mx1 = fmaxf(mx1, __shfl_xor_sync(0xffffffffu, mx1, off));
        }
        float mn0 = fmaxf(m0, mx0), mn1 = fmaxf(m1, mx1);
        float cr0 = __expf(m0 - mn0), cr1 = __expf(m1 - mn1);
        float sum0 = 0.0f, sum1 = 0.0f;
#pragma unroll
        for (int nt = 0; nt < 8; nt++) {
            s[nt][0] = __expf(s[nt][0] - mn0);
            s[nt][1] = __expf(s[nt][1] - mn0);
            s[nt][2] = __expf(s[nt][2] - mn1);
            s[nt][3] = __expf(s[nt][3] - mn1);
            sum0 += s[nt][0] + s[nt][1];
            sum1 += s[nt][2] + s[nt][3];
        }
#pragma unroll
        for (int off = 1; off < 4; off <<= 1) {
            sum0 += __shfl_xor_sync(0xffffffffu, sum0, off);
            sum1 += __shfl_xor_sync(0xffffffffu, sum1, off);
        }
        l0 = l0 * cr0 + sum0;  m0 = mn0;
        l1 = l1 * cr1 + sum1;  m1 = mn1;
#pragma unroll
        for (int nt = 0; nt < 8; nt++) {
            oacc[nt][0] *= cr0; oacc[nt][1] *= cr0;
            oacc[nt][2] *= cr1; oacc[nt][3] *= cr1;
        }

        // ---- stage P (tf32) ----
#pragma unroll
        for (int nt = 0; nt < 8; nt++) {
            Ps[(rb + g    ) * FSTR + nt * 8 + 2 * t    ] = f2tf(s[nt][0]);
            Ps[(rb + g    ) * FSTR + nt * 8 + 2 * t + 1] = f2tf(s[nt][1]);
            Ps[(rb + g + 8) * FSTR + nt * 8 + 2 * t    ] = f2tf(s[nt][2]);
            Ps[(rb + g + 8) * FSTR + nt * 8 + 2 * t + 1] = f2tf(s[nt][3]);
        }
        __syncwarp();

        // ---- O += P @ V ----
#pragma unroll
        for (int kk = 0; kk < 8; kk++) {
            const int kb = kk * 8;
            uint32_t a0 = __float_as_uint(Ps[(rb + g    ) * FSTR + kb + t    ]);
            uint32_t a1 = __float_as_uint(Ps[(rb + g + 8) * FSTR + kb + t    ]);
            uint32_t a2 = __float_as_uint(Ps[(rb + g    ) * FSTR + kb + t + 4]);
            uint32_t a3 = __float_as_uint(Ps[(rb + g + 8) * FSTR + kb + t + 4]);
#pragma unroll
            for (int nt = 0; nt < 8; nt++) {
                uint32_t b0 = __float_as_uint(Vs[(kb + t    ) * FSTR + nt * 8 + g]);
                uint32_t b1 = __float_as_uint(Vs[(kb + t + 4) * FSTR + nt * 8 + g]);
                mma_tf32(oacc[nt], a0, a1, a2, a3, b0, b1);
            }
        }
        __syncwarp();  // Ps reads done before next-iter overwrite
    }

    // ---- normalize + write ----
    float inv0 = 1.0f / l0, inv1 = 1.0f / l1;
#pragma unroll
    for (int nt = 0; nt < 8; nt++) {
        int c0 = nt * 8 + 2 * t;
        float2 v0 = make_float2(oacc[nt][0] * inv0, oacc[nt][1] * inv0);
        float2 v1 = make_float2(oacc[nt][2] * inv1, oacc[nt][3] * inv1);
        *(float2*)(O + baseQ + (size_t)(rb + g    ) * C_DIM + c0) = v0;
        *(float2*)(O + baseQ + (size_t)(rb + g + 8) * C_DIM + c0) = v1;
    }
}

// ---------------------------------------------------------------------------
// Launch
// ---------------------------------------------------------------------------
extern "C" void kernel_launch(void* const* d_in, const int* in_sizes, int n_in,
                              void* d_out, int out_size)
{
    const float* x     = (const float*)d_in[0];
    const float* q_w   = (const float*)d_in[1];
    const float* k_w   = (const float*)d_in[2];
    const float* v_mu  = (const float*)d_in[3];
    const float* v_rho = (const float*)d_in[4];
    const float* v_eps = (const float*)d_in[5];
    const float* p_mu  = (const float*)d_in[6];
    const float* p_rho = (const float*)d_in[7];
    const float* p_eps = (const float*)d_in[8];
    const float* pb_mu = (const float*)d_in[9];
    const float* pb_rho= (const float*)d_in[10];
    const float* pb_eps= (const float*)d_in[11];
    float* out = (float*)d_out;

    float *vw, *pw, *pb, *q, *k, *v, *o;
    cudaGetSymbolAddress((void**)&vw, g_vw);
    cudaGetSymbolAddress((void**)&pw, g_pw);
    cudaGetSymbolAddress((void**)&pb, g_pb);
    cudaGetSymbolAddress((void**)&q,  g_q);
    cudaGetSymbolAddress((void**)&k,  g_k);
    cudaGetSymbolAddress((void**)&v,  g_v);
    cudaGetSymbolAddress((void**)&o,  g_o);

    cudaFuncSetAttribute(flash_tf32,
                         cudaFuncAttributeMaxDynamicSharedMemorySize, FLASH_SMEM);

    const int nw = C_DIM * C_DIM;
    bayes_kernel<<<(nw + 255) / 256, 256>>>(v_mu, v_rho, v_eps, vw, nw);
    bayes_kernel<<<(nw + 255) / 256, 256>>>(p_mu, p_rho, p_eps, pw, nw);
    bayes_kernel<<<(C_DIM + 255) / 256, 256>>>(pb_mu, pb_rho, pb_eps, pb, C_DIM);

    dim3 ggrid(C_DIM / GBN, M_DIM / GBM);
    sgemm_tf32<<<ggrid, 256>>>(x, q_w, nullptr, q, C_DIM, C_DIM);
    sgemm_tf32<<<ggrid, 256>>>(x, k_w, nullptr, k, C_DIM, C_DIM);
    sgemm_tf32<<<ggrid, 256>>>(x, vw,  nullptr, v, C_DIM, C_DIM);

    flash_tf32<<<dim3(SEQ / 64, BATCH * H_DIM), 128, FLASH_SMEM>>>(q, k, v, o);

    sgemm_tf32<<<ggrid, 256>>>(o, pw, pb, out, C_DIM, C_DIM);
}

// round 5
// speedup vs baseline: 3.8896x; 1.2052x over previous
#include <cuda_runtime.h>
#include <math.h>
#include <stdint.h>

// Problem constants
#define BATCH  4
#define SEQ    2048
#define C_DIM  1024
#define H_DIM  16
#define D_DIM  64
#define M_DIM  (BATCH * SEQ)          // 8192
#define SCALE  0.125f                 // D^-0.5

// ---------------------------------------------------------------------------
// Device scratch
// ---------------------------------------------------------------------------
__device__ float g_vw [C_DIM * C_DIM];
__device__ float g_pw [C_DIM * C_DIM];
__device__ float g_pb [C_DIM];
__device__ float g_xr [M_DIM * C_DIM];
__device__ float g_qwr[C_DIM * C_DIM];
__device__ float g_kwr[C_DIM * C_DIM];
__device__ float g_q  [M_DIM * C_DIM];
__device__ float g_k  [M_DIM * C_DIM];
__device__ float g_v  [M_DIM * C_DIM];
__device__ float g_o  [M_DIM * C_DIM];

// ---------------------------------------------------------------------------
// Helpers
// ---------------------------------------------------------------------------
__device__ __forceinline__ float f2tf(float x) {
    uint32_t u;
    asm("cvt.rna.tf32.f32 %0, %1;" : "=r"(u) : "f"(x));
    return __uint_as_float(u);
}
__device__ __forceinline__ float4 f2tf4(float4 v) {
    v.x = f2tf(v.x); v.y = f2tf(v.y); v.z = f2tf(v.z); v.w = f2tf(v.w);
    return v;
}
__device__ __forceinline__ void mma_tf32(float* d,
                                         uint32_t a0, uint32_t a1, uint32_t a2, uint32_t a3,
                                         uint32_t b0, uint32_t b1)
{
    asm volatile(
        "mma.sync.aligned.m16n8k8.row.col.f32.tf32.tf32.f32 "
        "{%0,%1,%2,%3}, {%4,%5,%6,%7}, {%8,%9}, {%0,%1,%2,%3};\n"
        : "+f"(d[0]), "+f"(d[1]), "+f"(d[2]), "+f"(d[3])
        : "r"(a0), "r"(a1), "r"(a2), "r"(a3), "r"(b0), "r"(b1));
}
__device__ __forceinline__ void cp_async16(void* smem, const void* gmem) {
    uint32_t s = (uint32_t)__cvta_generic_to_shared(smem);
    asm volatile("cp.async.cg.shared.global [%0], [%1], 16;\n" :: "r"(s), "l"(gmem));
}
__device__ __forceinline__ void cp_commit() {
    asm volatile("cp.async.commit_group;\n");
}
template<int N> __device__ __forceinline__ void cp_wait() {
    asm volatile("cp.async.wait_group %0;\n" :: "n"(N));
}

// ---------------------------------------------------------------------------
// Elementwise prep kernels
// ---------------------------------------------------------------------------
__global__ void round_tf32_kernel(const float* __restrict__ in,
                                  float* __restrict__ out, int n4)
{
    int i = blockIdx.x * 256 + threadIdx.x;
    if (i < n4) ((float4*)out)[i] = f2tf4(((const float4*)in)[i]);
}

__global__ void bayes_kernel(const float* __restrict__ mu,
                             const float* __restrict__ rho,
                             const float* __restrict__ eps,
                             float* __restrict__ w, int n, int do_round)
{
    int i = blockIdx.x * 256 + threadIdx.x;
    if (i < n) {
        float r  = rho[i];
        float sp = (r > 15.0f) ? r : log1pf(__expf(r));
        float v  = fmaf(sp, eps[i], mu[i]);
        w[i] = do_round ? f2tf(v) : v;
    }
}

// ---------------------------------------------------------------------------
// TF32 SGEMM (NT) with 2-stage cp.async double buffering.
// C[m,n] = sum_k A[m,k]*B[n,k] (+ bias). Operands pre-rounded to tf32.
// 128x128x32 tile, 256 threads = 8 warps (2Mx4N), warp tile 64x32.
// ---------------------------------------------------------------------------
#define GBM 128
#define GBN 128
#define GBK 32
#define GSTR 36
#define GTILE (GBM * GSTR)
#define GEMM_SMEM (4 * GTILE * 4)   // 2 stages x (A+B) x 4B = 73728 B

__global__ __launch_bounds__(256, 2)
void sgemm_tf32(const float* __restrict__ A, const float* __restrict__ B,
                const float* __restrict__ bias, float* __restrict__ Cmat,
                int Kdim, int Ndim, int round_out)
{
    extern __shared__ float sm[];
    float* As = sm;                // [2][GTILE]
    float* Bs = sm + 2 * GTILE;    // [2][GTILE]

    const int tid  = threadIdx.x;
    const int lane = tid & 31;
    const int w    = tid >> 5;
    const int wm   = w >> 2;
    const int wn   = w & 3;
    const int g    = lane >> 2;
    const int t    = lane & 3;
    const int m0   = blockIdx.y * GBM;
    const int n0   = blockIdx.x * GBN;

    float acc[4][4][4];
#pragma unroll
    for (int i = 0; i < 4; i++)
#pragma unroll
        for (int j = 0; j < 4; j++)
#pragma unroll
            for (int c = 0; c < 4; c++) acc[i][j][c] = 0.0f;

    // Rows are GBK=32 floats wide: 8 threads x 4-float segments per row.
    const int lrow = tid >> 3;              // 0..31
    const int lsg  = (tid & 7) * 4;         // 0,4,...,28

    #define LOAD_TILES(st, k0)                                                  \
        do {                                                                    \
            _Pragma("unroll")                                                   \
            for (int it = 0; it < 4; it++) {                                    \
                int row = lrow + it * 32;                                       \
                cp_async16(&As[(st) * GTILE + row * GSTR + lsg],                \
                           A + (size_t)(m0 + row) * Kdim + (k0) + lsg);         \
                cp_async16(&Bs[(st) * GTILE + row * GSTR + lsg],                \
                           B + (size_t)(n0 + row) * Kdim + (k0) + lsg);         \
            }                                                                   \
            cp_commit();                                                        \
        } while (0)

    LOAD_TILES(0, 0);

    int st = 0;
    for (int k0 = 0; k0 < Kdim; k0 += GBK) {
        if (k0 + GBK < Kdim) { LOAD_TILES(st ^ 1, k0 + GBK); cp_wait<1>(); }
        else                 { cp_wait<0>(); }
        __syncthreads();

        const float* Ac = As + st * GTILE;
        const float* Bc = Bs + st * GTILE;
#pragma unroll
        for (int kk = 0; kk < 4; kk++) {
            const int kb = kk * 8;
            uint32_t af[4][4];
#pragma unroll
            for (int mt = 0; mt < 4; mt++) {
                int rb = wm * 64 + mt * 16;
                af[mt][0] = __float_as_uint(Ac[(rb + g    ) * GSTR + kb + t    ]);
                af[mt][1] = __float_as_uint(Ac[(rb + g + 8) * GSTR + kb + t    ]);
                af[mt][2] = __float_as_uint(Ac[(rb + g    ) * GSTR + kb + t + 4]);
                af[mt][3] = __float_as_uint(Ac[(rb + g + 8) * GSTR + kb + t + 4]);
            }
            uint32_t bf[4][2];
#pragma unroll
            for (int nt = 0; nt < 4; nt++) {
                int cb = wn * 32 + nt * 8;
                bf[nt][0] = __float_as_uint(Bc[(cb + g) * GSTR + kb + t    ]);
                bf[nt][1] = __float_as_uint(Bc[(cb + g) * GSTR + kb + t + 4]);
            }
#pragma unroll
            for (int mt = 0; mt < 4; mt++)
#pragma unroll
                for (int nt = 0; nt < 4; nt++)
                    mma_tf32(acc[mt][nt], af[mt][0], af[mt][1], af[mt][2], af[mt][3],
                             bf[nt][0], bf[nt][1]);
        }
        __syncthreads();
        st ^= 1;
    }
    #undef LOAD_TILES

    // Epilogue
#pragma unroll
    for (int mt = 0; mt < 4; mt++) {
        int r0 = m0 + wm * 64 + mt * 16 + g;
#pragma unroll
        for (int nt = 0; nt < 4; nt++) {
            int c0 = n0 + wn * 32 + nt * 8 + 2 * t;
            float bx = 0.0f, by = 0.0f;
            if (bias) { bx = bias[c0]; by = bias[c0 + 1]; }
            float2 v0 = make_float2(acc[mt][nt][0] + bx, acc[mt][nt][1] + by);
            float2 v1 = make_float2(acc[mt][nt][2] + bx, acc[mt][nt][3] + by);
            if (round_out) {
                v0.x = f2tf(v0.x); v0.y = f2tf(v0.y);
                v1.x = f2tf(v1.x); v1.y = f2tf(v1.y);
            }
            *(float2*)(Cmat + (size_t)r0 * Ndim + c0)       = v0;
            *(float2*)(Cmat + (size_t)(r0 + 8) * Ndim + c0) = v1;
        }
    }
}

// ---------------------------------------------------------------------------
// TF32 flash attention with 2-stage cp.async K/V double buffering.
// 128 threads = 4 warps; warp owns 16 S-rows. BQ = BK = 64, D = 64.
// Tile rows are 64 floats wide: 16 threads x 4-float segments per row.
// ---------------------------------------------------------------------------
#define FSTR 68
#define FTILE (64 * FSTR)
#define FLASH_SMEM (6 * FTILE * 4)   // Q + 2K + 2V + P = 104448 B

__global__ __launch_bounds__(128, 2)
void flash_tf32(const float* __restrict__ Q, const float* __restrict__ K,
                const float* __restrict__ V, float* __restrict__ O)
{
    extern __shared__ float sm[];
    float* Qs = sm;                  // [64][FSTR]
    float* Ks = sm + 1 * FTILE;      // [2][64][FSTR]
    float* Vs = sm + 3 * FTILE;      // [2][64][FSTR]
    float* Ps = sm + 5 * FTILE;      // [64][FSTR]

    const int tid  = threadIdx.x;
    const int lane = tid & 31;
    const int w    = tid >> 5;
    const int g    = lane >> 2;
    const int t    = lane & 3;
    const int rb   = w * 16;
    const int bh   = blockIdx.y;
    const int b    = bh >> 4;
    const int h    = bh & 15;
    const int q0   = blockIdx.x * 64;

    const size_t baseQ  = ((size_t)b * SEQ + q0) * C_DIM + h * D_DIM;
    const size_t baseKV = ((size_t)b * SEQ) * C_DIM + h * D_DIM;

    // 64-wide rows: 16 threads per row, 8 row-groups of 8.
    const int lrow = tid >> 4;            // 0..7
    const int ldq  = (tid & 15) * 4;      // 0,4,...,60

    // Q tile (pre-rounded): full 64x64 coverage, 8 iterations.
#pragma unroll
    for (int it = 0; it < 8; it++) {
        int row = lrow + it * 8;
        *(float4*)&Qs[row * FSTR + ldq] =
            *(const float4*)(Q + baseQ + (size_t)row * C_DIM + ldq);
    }

    #define LOAD_KV(st, kt)                                                     \
        do {                                                                    \
            _Pragma("unroll")                                                   \
            for (int it = 0; it < 8; it++) {                                    \
                int row = lrow + it * 8;                                        \
                cp_async16(&Ks[(st) * FTILE + row * FSTR + ldq],                \
                           K + baseKV + (size_t)((kt) + row) * C_DIM + ldq);    \
                cp_async16(&Vs[(st) * FTILE + row * FSTR + ldq],                \
                           V + baseKV + (size_t)((kt) + row) * C_DIM + ldq);    \
            }                                                                   \
            cp_commit();                                                        \
        } while (0)

    LOAD_KV(0, 0);

    float m0 = -1e30f, m1 = -1e30f, l0 = 0.0f, l1 = 0.0f;
    float oacc[8][4];
#pragma unroll
    for (int nt = 0; nt < 8; nt++)
#pragma unroll
        for (int c = 0; c < 4; c++) oacc[nt][c] = 0.0f;

    int st = 0;
    for (int kt = 0; kt < SEQ; kt += 64) {
        if (kt + 64 < SEQ) { LOAD_KV(st ^ 1, kt + 64); cp_wait<1>(); }
        else               { cp_wait<0>(); }
        __syncthreads();

        const float* Kc = Ks + st * FTILE;
        const float* Vc = Vs + st * FTILE;

        // ---- S = Q @ K^T ----
        float s[8][4];
#pragma unroll
        for (int nt = 0; nt < 8; nt++)
#pragma unroll
            for (int c = 0; c < 4; c++) s[nt][c] = 0.0f;

#pragma unroll
        for (int kk = 0; kk < 8; kk++) {
            const int kb = kk * 8;
            uint32_t a0 = __float_as_uint(Qs[(rb + g    ) * FSTR + kb + t    ]);
            uint32_t a1 = __float_as_uint(Qs[(rb + g + 8) * FSTR + kb + t    ]);
            uint32_t a2 = __float_as_uint(Qs[(rb + g    ) * FSTR + kb + t + 4]);
            uint32_t a3 = __float_as_uint(Qs[(rb + g + 8) * FSTR + kb + t + 4]);
#pragma unroll
            for (int nt = 0; nt < 8; nt++) {
                uint32_t b0 = __float_as_uint(Kc[(nt * 8 + g) * FSTR + kb + t    ]);
                uint32_t b1 = __float_as_uint(Kc[(nt * 8 + g) * FSTR + kb + t + 4]);
                mma_tf32(s[nt], a0, a1, a2, a3, b0, b1);
            }
        }

        // ---- online softmax ----
        float mx0 = -1e30f, mx1 = -1e30f;
#pragma unroll
        for (int nt = 0; nt < 8; nt++) {
            s[nt][0] *= SCALE; s[nt][1] *= SCALE;
            s[nt][2] *= SCALE; s[nt][3] *= SCALE;
            mx0 = fmaxf(mx0, fmaxf(s[nt][0], s[nt][1]));
            mx1 = fmaxf(mx1, fmaxf(s[nt][2], s[nt][3]));
        }
#pragma unroll
        for (int off = 1; off < 4; off <<= 1) {
            mx0 = fmaxf(mx0, __shfl_xor_sync(0xffffffffu, mx0, off));
            mx1 = fmaxf(mx1, __shfl_xor_sync(0xffffffffu, mx1, off));
        }
        float mn0 = fmaxf(m0, mx0), mn1 = fmaxf(m1, mx1);
        float cr0 = __expf(m0 - mn0), cr1 = __expf(m1 - mn1);
        float sum0 = 0.0f, sum1 = 0.0f;
#pragma unroll
        for (int nt = 0; nt < 8; nt++) {
            s[nt][0] = __expf(s[nt][0] - mn0);
            s[nt][1] = __expf(s[nt][1] - mn0);
            s[nt][2] = __expf(s[nt][2] - mn1);
            s[nt][3] = __expf(s[nt][3] - mn1);
            sum0 += s[nt][0] + s[nt][1];
            sum1 += s[nt][2] + s[nt][3];
        }
#pragma unroll
        for (int off = 1; off < 4; off <<= 1) {
            sum0 += __shfl_xor_sync(0xffffffffu, sum0, off);
            sum1 += __shfl_xor_sync(0xffffffffu, sum1, off);
        }
        l0 = l0 * cr0 + sum0;  m0 = mn0;
        l1 = l1 * cr1 + sum1;  m1 = mn1;
#pragma unroll
        for (int nt = 0; nt < 8; nt++) {
            oacc[nt][0] *= cr0; oacc[nt][1] *= cr0;
            oacc[nt][2] *= cr1; oacc[nt][3] *= cr1;
        }

        // ---- stage P ----
#pragma unroll
        for (int nt = 0; nt < 8; nt++) {
            Ps[(rb + g    ) * FSTR + nt * 8 + 2 * t    ] = f2tf(s[nt][0]);
            Ps[(rb + g    ) * FSTR + nt * 8 + 2 * t + 1] = f2tf(s[nt][1]);
            Ps[(rb + g + 8) * FSTR + nt * 8 + 2 * t    ] = f2tf(s[nt][2]);
            Ps[(rb + g + 8) * FSTR + nt * 8 + 2 * t + 1] = f2tf(s[nt][3]);
        }
        __syncwarp();

        // ---- O += P @ V ----
#pragma unroll
        for (int kk = 0; kk < 8; kk++) {
            const int kb = kk * 8;
            uint32_t a0 = __float_as_uint(Ps[(rb + g    ) * FSTR + kb + t    ]);
            uint32_t a1 = __float_as_uint(Ps[(rb + g + 8) * FSTR + kb + t    ]);
            uint32_t a2 = __float_as_uint(Ps[(rb + g    ) * FSTR + kb + t + 4]);
            uint32_t a3 = __float_as_uint(Ps[(rb + g + 8) * FSTR + kb + t + 4]);
#pragma unroll
            for (int nt = 0; nt < 8; nt++) {
                uint32_t b0 = __float_as_uint(Vc[(kb + t    ) * FSTR + nt * 8 + g]);
                uint32_t b1 = __float_as_uint(Vc[(kb + t + 4) * FSTR + nt * 8 + g]);
                mma_tf32(oacc[nt], a0, a1, a2, a3, b0, b1);
            }
        }
        __syncthreads();
        st ^= 1;
    }
    #undef LOAD_KV

    // ---- normalize + write (rounded: feeds final GEMM) ----
    float inv0 = 1.0f / l0, inv1 = 1.0f / l1;
#pragma unroll
    for (int nt = 0; nt < 8; nt++) {
        int c0 = nt * 8 + 2 * t;
        float2 v0 = make_float2(f2tf(oacc[nt][0] * inv0), f2tf(oacc[nt][1] * inv0));
        float2 v1 = make_float2(f2tf(oacc[nt][2] * inv1), f2tf(oacc[nt][3] * inv1));
        *(float2*)(O + baseQ + (size_t)(rb + g    ) * C_DIM + c0) = v0;
        *(float2*)(O + baseQ + (size_t)(rb + g + 8) * C_DIM + c0) = v1;
    }
}

// ---------------------------------------------------------------------------
// Launch
// ---------------------------------------------------------------------------
extern "C" void kernel_launch(void* const* d_in, const int* in_sizes, int n_in,
                              void* d_out, int out_size)
{
    const float* x     = (const float*)d_in[0];
    const float* q_w   = (const float*)d_in[1];
    const float* k_w   = (const float*)d_in[2];
    const float* v_mu  = (const float*)d_in[3];
    const float* v_rho = (const float*)d_in[4];
    const float* v_eps = (const float*)d_in[5];
    const float* p_mu  = (const float*)d_in[6];
    const float* p_rho = (const float*)d_in[7];
    const float* p_eps = (const float*)d_in[8];
    const float* pb_mu = (const float*)d_in[9];
    const float* pb_rho= (const float*)d_in[10];
    const float* pb_eps= (const float*)d_in[11];
    float* out = (float*)d_out;

    float *vw, *pw, *pb, *xr, *qwr, *kwr, *q, *k, *v, *o;
    cudaGetSymbolAddress((void**)&vw,  g_vw);
    cudaGetSymbolAddress((void**)&pw,  g_pw);
    cudaGetSymbolAddress((void**)&pb,  g_pb);
    cudaGetSymbolAddress((void**)&xr,  g_xr);
    cudaGetSymbolAddress((void**)&qwr, g_qwr);
    cudaGetSymbolAddress((void**)&kwr, g_kwr);
    cudaGetSymbolAddress((void**)&q,   g_q);
    cudaGetSymbolAddress((void**)&k,   g_k);
    cudaGetSymbolAddress((void**)&v,   g_v);
    cudaGetSymbolAddress((void**)&o,   g_o);

    cudaFuncSetAttribute(sgemm_tf32,
                         cudaFuncAttributeMaxDynamicSharedMemorySize, GEMM_SMEM);
    cudaFuncSetAttribute(flash_tf32,
                         cudaFuncAttributeMaxDynamicSharedMemorySize, FLASH_SMEM);

    const int nw  = C_DIM * C_DIM;
    const int nw4 = nw / 4;
    const int nx4 = M_DIM * C_DIM / 4;

    round_tf32_kernel<<<(nx4 + 255) / 256, 256>>>(x,   xr,  nx4);
    round_tf32_kernel<<<(nw4 + 255) / 256, 256>>>(q_w, qwr, nw4);
    round_tf32_kernel<<<(nw4 + 255) / 256, 256>>>(k_w, kwr, nw4);
    bayes_kernel<<<(nw + 255) / 256, 256>>>(v_mu, v_rho, v_eps, vw, nw, 1);
    bayes_kernel<<<(nw + 255) / 256, 256>>>(p_mu, p_rho, p_eps, pw, nw, 1);
    bayes_kernel<<<(C_DIM + 255) / 256, 256>>>(pb_mu, pb_rho, pb_eps, pb, C_DIM, 0);

    dim3 ggrid(C_DIM / GBN, M_DIM / GBM);
    sgemm_tf32<<<ggrid, 256, GEMM_SMEM>>>(xr, qwr, nullptr, q, C_DIM, C_DIM, 1);
    sgemm_tf32<<<ggrid, 256, GEMM_SMEM>>>(xr, kwr, nullptr, k, C_DIM, C_DIM, 1);
    sgemm_tf32<<<ggrid, 256, GEMM_SMEM>>>(xr, vw,  nullptr, v, C_DIM, C_DIM, 1);

    flash_tf32<<<dim3(SEQ / 64, BATCH * H_DIM), 128, FLASH_SMEM>>>(q, k, v, o);

    sgemm_tf32<<<ggrid, 256, GEMM_SMEM>>>(o, pw, pb, out, C_DIM, C_DIM, 0);
}

// round 7
// speedup vs baseline: 4.5900x; 1.1801x over previous
#include <cuda_runtime.h>
#include <math.h>
#include <stdint.h>

// Problem constants
#define BATCH  4
#define SEQ    2048
#define C_DIM  1024
#define H_DIM  16
#define D_DIM  64
#define M_DIM  (BATCH * SEQ)          // 8192
// softmax scale folded into q weights: D^-0.5 * log2(e)
#define QSCALE (0.125f * 1.4426950408889634f)

// ---------------------------------------------------------------------------
// Device scratch
// ---------------------------------------------------------------------------
__device__ float g_vw [C_DIM * C_DIM];
__device__ float g_pw [C_DIM * C_DIM];
__device__ float g_pb [C_DIM];
__device__ float g_xr [M_DIM * C_DIM];
__device__ float g_qwr[C_DIM * C_DIM];
__device__ float g_kwr[C_DIM * C_DIM];
__device__ float g_q  [M_DIM * C_DIM];
__device__ float g_k  [M_DIM * C_DIM];
__device__ float g_v  [M_DIM * C_DIM];
__device__ float g_o  [M_DIM * C_DIM];

// ---------------------------------------------------------------------------
// Helpers
// ---------------------------------------------------------------------------
__device__ __forceinline__ float f2tf(float x) {
    uint32_t u;
    asm("cvt.rna.tf32.f32 %0, %1;" : "=r"(u) : "f"(x));
    return __uint_as_float(u);
}
__device__ __forceinline__ float4 f2tf4(float4 v) {
    v.x = f2tf(v.x); v.y = f2tf(v.y); v.z = f2tf(v.z); v.w = f2tf(v.w);
    return v;
}
__device__ __forceinline__ float ex2f(float x) {
    float y;
    asm("ex2.approx.f32 %0, %1;" : "=f"(y) : "f"(x));
    return y;
}
__device__ __forceinline__ void mma_tf32(float* d,
                                         uint32_t a0, uint32_t a1, uint32_t a2, uint32_t a3,
                                         uint32_t b0, uint32_t b1)
{
    asm volatile(
        "mma.sync.aligned.m16n8k8.row.col.f32.tf32.tf32.f32 "
        "{%0,%1,%2,%3}, {%4,%5,%6,%7}, {%8,%9}, {%0,%1,%2,%3};\n"
        : "+f"(d[0]), "+f"(d[1]), "+f"(d[2]), "+f"(d[3])
        : "r"(a0), "r"(a1), "r"(a2), "r"(a3), "r"(b0), "r"(b1));
}
__device__ __forceinline__ void ldsm_x4(uint32_t& r0, uint32_t& r1,
                                        uint32_t& r2, uint32_t& r3, uint32_t addr)
{
    asm volatile("ldmatrix.sync.aligned.m8n8.x4.shared.b16 {%0,%1,%2,%3}, [%4];"
                 : "=r"(r0), "=r"(r1), "=r"(r2), "=r"(r3) : "r"(addr));
}
__device__ __forceinline__ uint32_t smem_u32(const void* p) {
    return (uint32_t)__cvta_generic_to_shared(p);
}
__device__ __forceinline__ void cp_async16(void* smem, const void* gmem) {
    uint32_t s = smem_u32(smem);
    asm volatile("cp.async.cg.shared.global [%0], [%1], 16;\n" :: "r"(s), "l"(gmem));
}
__device__ __forceinline__ void cp_commit() {
    asm volatile("cp.async.commit_group;\n");
}
template<int N> __device__ __forceinline__ void cp_wait() {
    asm volatile("cp.async.wait_group %0;\n" :: "n"(N));
}
__device__ __forceinline__ float bayes_w(float mu, float rho, float eps) {
    float sp = (rho > 15.0f) ? rho : log1pf(__expf(rho));
    return fmaf(sp, eps, mu);
}

// ---------------------------------------------------------------------------
// Prep kernels (2 launches so flash is the 6th launch -> ncu captures it)
// ---------------------------------------------------------------------------
__global__ void round_x_kernel(const float* __restrict__ in,
                               float* __restrict__ out, int n4)
{
    int i = blockIdx.x * 256 + threadIdx.x;
    if (i < n4) ((float4*)out)[i] = f2tf4(((const float4*)in)[i]);
}

__global__ void prep_w_kernel(const float* __restrict__ qw,  const float* __restrict__ kw,
                              const float* __restrict__ vmu, const float* __restrict__ vrho,
                              const float* __restrict__ veps,
                              const float* __restrict__ pmu, const float* __restrict__ prho,
                              const float* __restrict__ peps,
                              const float* __restrict__ pbmu, const float* __restrict__ pbrho,
                              const float* __restrict__ pbeps,
                              float* __restrict__ qwr, float* __restrict__ kwr,
                              float* __restrict__ vw,  float* __restrict__ pw,
                              float* __restrict__ pb)
{
    const int nw = C_DIM * C_DIM;
    int i = blockIdx.x * 256 + threadIdx.x;
    if (i < nw) {
        qwr[i] = f2tf(qw[i] * QSCALE);          // softmax scale folded here
    } else if (i < 2 * nw) {
        int j = i - nw;      kwr[j] = f2tf(kw[j]);
    } else if (i < 3 * nw) {
        int j = i - 2 * nw;  vw[j] = f2tf(bayes_w(vmu[j], vrho[j], veps[j]));
    } else if (i < 4 * nw) {
        int j = i - 3 * nw;  pw[j] = f2tf(bayes_w(pmu[j], prho[j], peps[j]));
    } else if (i < 4 * nw + C_DIM) {
        int j = i - 4 * nw;  pb[j] = bayes_w(pbmu[j], pbrho[j], pbeps[j]);
    }
}

// ---------------------------------------------------------------------------
// TF32 SGEMM (NT): 2-stage cp.async + ldmatrix fragment loads.
// 128x128x32 tile, 256 threads = 8 warps (2Mx4N), warp tile 64x32.
// ---------------------------------------------------------------------------
#define GBM 128
#define GBN 128
#define GBK 32
#define GSTR 36
#define GTILE (GBM * GSTR)
#define GEMM_SMEM (4 * GTILE * 4)   // 73728 B

__global__ __launch_bounds__(256, 2)
void sgemm_tf32(const float* __restrict__ A, const float* __restrict__ B,
                const float* __restrict__ bias, float* __restrict__ Cmat,
                int Kdim, int Ndim, int round_out)
{
    extern __shared__ float sm[];
    float* As = sm;                // [2][GTILE]
    float* Bs = sm + 2 * GTILE;    // [2][GTILE]

    const int tid  = threadIdx.x;
    const int lane = tid & 31;
    const int w    = tid >> 5;
    const int wm   = w >> 2;
    const int wn   = w & 3;
    const int g    = lane >> 2;
    const int t    = lane & 3;
    const int m0   = blockIdx.y * GBM;
    const int n0   = blockIdx.x * GBN;

    // ldmatrix per-lane byte offsets (A pattern / B pattern)
    const uint32_t offA = ((lane & 15) * GSTR) * 4 + (lane >> 4) * 16;
    const uint32_t offB = (((lane & 7) + ((lane & 16) >> 1)) * GSTR) * 4 +
                          ((lane >> 3) & 1) * 16;
    const uint32_t uAs = smem_u32(As);
    const uint32_t uBs = smem_u32(Bs);

    float acc[4][4][4];
#pragma unroll
    for (int i = 0; i < 4; i++)
#pragma unroll
        for (int j = 0; j < 4; j++)
#pragma unroll
            for (int c = 0; c < 4; c++) acc[i][j][c] = 0.0f;

    const int lrow = tid >> 3;              // 0..31
    const int lsg  = (tid & 7) * 4;         // 0,4,...,28

    #define LOAD_TILES(st, k0)                                                  \
        do {                                                                    \
            _Pragma("unroll")                                                   \
            for (int it = 0; it < 4; it++) {                                    \
                int row = lrow + it * 32;                                       \
                cp_async16(&As[(st) * GTILE + row * GSTR + lsg],                \
                           A + (size_t)(m0 + row) * Kdim + (k0) + lsg);         \
                cp_async16(&Bs[(st) * GTILE + row * GSTR + lsg],                \
                           B + (size_t)(n0 + row) * Kdim + (k0) + lsg);         \
            }                                                                   \
            cp_commit();                                                        \
        } while (0)

    LOAD_TILES(0, 0);

    int st = 0;
    for (int k0 = 0; k0 < Kdim; k0 += GBK) {
        if (k0 + GBK < Kdim) { LOAD_TILES(st ^ 1, k0 + GBK); cp_wait<1>(); }
        else                 { cp_wait<0>(); }
        __syncthreads();

        const uint32_t aBase = uAs + st * GTILE * 4;
        const uint32_t bBase = uBs + st * GTILE * 4;
#pragma unroll
        for (int kk = 0; kk < 4; kk++) {
            const uint32_t kbB = kk * 32;   // kk*8 floats
            uint32_t af[4][4];
#pragma unroll
            for (int mt = 0; mt < 4; mt++)
                ldsm_x4(af[mt][0], af[mt][1], af[mt][2], af[mt][3],
                        aBase + (uint32_t)(wm * 64 + mt * 16) * GSTR * 4 + offA + kbB);
            uint32_t bf[4][2];
#pragma unroll
            for (int p = 0; p < 2; p++)
                ldsm_x4(bf[2 * p][0], bf[2 * p][1], bf[2 * p + 1][0], bf[2 * p + 1][1],
                        bBase + (uint32_t)(wn * 32 + p * 16) * GSTR * 4 + offB + kbB);
#pragma unroll
            for (int mt = 0; mt < 4; mt++)
#pragma unroll
                for (int nt = 0; nt < 4; nt++)
                    mma_tf32(acc[mt][nt], af[mt][0], af[mt][1], af[mt][2], af[mt][3],
                             bf[nt][0], bf[nt][1]);
        }
        __syncthreads();
        st ^= 1;
    }
    #undef LOAD_TILES

    // Epilogue
#pragma unroll
    for (int mt = 0; mt < 4; mt++) {
        int r0 = m0 + wm * 64 + mt * 16 + g;
#pragma unroll
        for (int nt = 0; nt < 4; nt++) {
            int c0 = n0 + wn * 32 + nt * 8 + 2 * t;
            float bx = 0.0f, by = 0.0f;
            if (bias) { bx = bias[c0]; by = bias[c0 + 1]; }
            float2 v0 = make_float2(acc[mt][nt][0] + bx, acc[mt][nt][1] + by);
            float2 v1 = make_float2(acc[mt][nt][2] + bx, acc[mt][nt][3] + by);
            if (round_out) {
                v0.x = f2tf(v0.x); v0.y = f2tf(v0.y);
                v1.x = f2tf(v1.x); v1.y = f2tf(v1.y);
            }
            *(float2*)(Cmat + (size_t)r0 * Ndim + c0)       = v0;
            *(float2*)(Cmat + (size_t)(r0 + 8) * Ndim + c0) = v1;
        }
    }
}

// ---------------------------------------------------------------------------
// TF32 flash attention: cp.async K/V double buffering, Q frags in registers,
// ldmatrix for K/P fragments, conflict-free V stride, base-2 softmax.
// 128 threads = 4 warps; warp owns 16 S-rows. BQ = BK = 64, D = 64.
// ---------------------------------------------------------------------------
#define FSTR  68                   // K/P row stride (floats), % 32 banks = 4
#define VSTR  72                   // V row stride, % 32 banks = 8 -> (8t+g) conflict-free
#define KTILE (64 * FSTR)          // 4352 floats
#define VTILE (64 * VSTR)          // 4608 floats
#define FLASH_SMEM ((2 * KTILE + 2 * VTILE + KTILE) * 4)   // 89088 B

__global__ __launch_bounds__(128, 2)
void flash_tf32(const float* __restrict__ Q, const float* __restrict__ K,
                const float* __restrict__ V, float* __restrict__ O)
{
    extern __shared__ float sm[];
    float* Ks = sm;                          // [2][KTILE]
    float* Vs = sm + 2 * KTILE;              // [2][VTILE]
    float* Ps = sm + 2 * KTILE + 2 * VTILE;  // [KTILE], also Q staging

    const int tid  = threadIdx.x;
    const int lane = tid & 31;
    const int w    = tid >> 5;
    const int g    = lane >> 2;
    const int t    = lane & 3;
    const int rb   = w * 16;
    const int bh   = blockIdx.y;
    const int b    = bh >> 4;
    const int h    = bh & 15;
    const int q0   = blockIdx.x * 64;

    const size_t baseQ  = ((size_t)b * SEQ + q0) * C_DIM + h * D_DIM;
    const size_t baseKV = ((size_t)b * SEQ) * C_DIM + h * D_DIM;

    const int lrow = tid >> 4;            // 0..7
    const int ldq  = (tid & 15) * 4;      // 0,4,...,60

    const uint32_t uKs = smem_u32(Ks);
    const uint32_t uPs = smem_u32(Ps);
    // ldmatrix per-lane byte offsets
    const uint32_t offA = ((lane & 15) * FSTR) * 4 + (lane >> 4) * 16;   // Q/P pattern
    const uint32_t offB = (((lane & 7) + ((lane & 16) >> 1)) * FSTR) * 4 +
                          ((lane >> 3) & 1) * 16;                        // K pattern

    #define LOAD_KV(st, kt)                                                     \
        do {                                                                    \
            _Pragma("unroll")                                                   \
            for (int it = 0; it < 8; it++) {                                    \
                int row = lrow + it * 8;                                        \
                cp_async16(&Ks[(st) * KTILE + row * FSTR + ldq],                \
                           K + baseKV + (size_t)((kt) + row) * C_DIM + ldq);    \
                cp_async16(&Vs[(st) * VTILE + row * VSTR + ldq],                \
                           V + baseKV + (size_t)((kt) + row) * C_DIM + ldq);    \
            }                                                                   \
            cp_commit();                                                        \
        } while (0)

    LOAD_KV(0, 0);

    // Stage Q (pre-rounded, pre-scaled) into Ps, then hoist fragments to regs.
#pragma unroll
    for (int it = 0; it < 8; it++) {
        int row = lrow + it * 8;
        *(float4*)&Ps[row * FSTR + ldq] =
            *(const float4*)(Q + baseQ + (size_t)row * C_DIM + ldq);
    }
    __syncthreads();

    uint32_t qf[8][4];
#pragma unroll
    for (int kk = 0; kk < 8; kk++)
        ldsm_x4(qf[kk][0], qf[kk][1], qf[kk][2], qf[kk][3],
                uPs + (uint32_t)rb * FSTR * 4 + offA + kk * 32);

    float m0 = -1e30f, m1 = -1e30f, l0 = 0.0f, l1 = 0.0f;
    float oacc[8][4];
#pragma unroll
    for (int nt = 0; nt < 8; nt++)
#pragma unroll
        for (int c = 0; c < 4; c++) oacc[nt][c] = 0.0f;

    int st = 0;
    for (int kt = 0; kt < SEQ; kt += 64) {
        if (kt + 64 < SEQ) { LOAD_KV(st ^ 1, kt + 64); cp_wait<1>(); }
        else               { cp_wait<0>(); }
        __syncthreads();

        const uint32_t kBase = uKs + st * KTILE * 4;
        const float*   Vc    = Vs + st * VTILE;

        // ---- S = Q @ K^T (values already scaled by D^-0.5 * log2e) ----
        float s[8][4];
#pragma unroll
        for (int nt = 0; nt < 8; nt++)
#pragma unroll
            for (int c = 0; c < 4; c++) s[nt][c] = 0.0f;

#pragma unroll
        for (int kk = 0; kk < 8; kk++) {
            const uint32_t kbB = kk * 32;
#pragma unroll
            for (int p = 0; p < 4; p++) {
                uint32_t b0, b1, b2, b3;
                ldsm_x4(b0, b1, b2, b3,
                        kBase + (uint32_t)(p * 16) * FSTR * 4 + offB + kbB);
                mma_tf32(s[2 * p],     qf[kk][0], qf[kk][1], qf[kk][2], qf[kk][3], b0, b1);
                mma_tf32(s[2 * p + 1], qf[kk][0], qf[kk][1], qf[kk][2], qf[kk][3], b2, b3);
            }
        }

        // ---- online softmax (base 2) ----
        float mx0 = -1e30f, mx1 = -1e30f;
#pragma unroll
        for (int nt = 0; nt < 8; nt++) {
            mx0 = fmaxf(mx0, fmaxf(s[nt][0], s[nt][1]));
            mx1 = fmaxf(mx1, fmaxf(s[nt][2], s[nt][3]));
        }
#pragma unroll
        for (int off = 1; off < 4; off <<= 1) {
            mx0 = fmaxf(mx0, __shfl_xor_sync(0xffffffffu, mx0, off));
            mx1 = fmaxf(mx1, __shfl_xor_sync(0xffffffffu, mx1, off));
        }
        float mn0 = fmaxf(m0, mx0), mn1 = fmaxf(m1, mx1);
        float cr0 = ex2f(m0 - mn0), cr1 = ex2f(m1 - mn1);
        float sum0 = 0.0f, sum1 = 0.0f;
#pragma unroll
        for (int nt = 0; nt < 8; nt++) {
            s[nt][0] = ex2f(s[nt][0] - mn0);
            s[nt][1] = ex2f(s[nt][1] - mn0);
            s[nt][2] = ex2f(s[nt][2] - mn1);
            s[nt][3] = ex2f(s[nt][3] - mn1);
            sum0 += s[nt][0] + s[nt][1];
            sum1 += s[nt][2] + s[nt][3];
        }
#pragma unroll
        for (int off = 1; off < 4; off <<= 1) {
            sum0 += __shfl_xor_sync(0xffffffffu, sum0, off);
            sum1 += __shfl_xor_sync(0xffffffffu, sum1, off);
        }
        l0 = l0 * cr0 + sum0;  m0 = mn0;
        l1 = l1 * cr1 + sum1;  m1 = mn1;
#pragma unroll
        for (int nt = 0; nt < 8; nt++) {
            oacc[nt][0] *= cr0; oacc[nt][1] *= cr0;
            oacc[nt][2] *= cr1; oacc[nt][3] *= cr1;
        }

        // ---- stage P (tf32, float2 stores into own warp's rows) ----
#pragma unroll
        for (int nt = 0; nt < 8; nt++) {
            *(float2*)&Ps[(rb + g    ) * FSTR + nt * 8 + 2 * t] =
                make_float2(f2tf(s[nt][0]), f2tf(s[nt][1]));
            *(float2*)&Ps[(rb + g + 8) * FSTR + nt * 8 + 2 * t] =
                make_float2(f2tf(s[nt][2]), f2tf(s[nt][3]));
        }
        __syncwarp();

        // ---- O += P @ V ----
#pragma unroll
        for (int kk = 0; kk < 8; kk++) {
            const int kb = kk * 8;
            uint32_t a0, a1, a2, a3;
            ldsm_x4(a0, a1, a2, a3,
                    uPs + (uint32_t)rb * FSTR * 4 + offA + kk * 32);
#pragma unroll
            for (int nt = 0; nt < 8; nt++) {
                uint32_t b0 = __float_as_uint(Vc[(kb + t    ) * VSTR + nt * 8 + g]);
                uint32_t b1 = __float_as_uint(Vc[(kb + t + 4) * VSTR + nt * 8 + g]);
                mma_tf32(oacc[nt], a0, a1, a2, a3, b0, b1);
            }
        }
        __syncthreads();
        st ^= 1;
    }
    #undef LOAD_KV

    // ---- normalize + write (rounded: feeds final GEMM) ----
    float inv0 = 1.0f / l0, inv1 = 1.0f / l1;
#pragma unroll
    for (int nt = 0; nt < 8; nt++) {
        int c0 = nt * 8 + 2 * t;
        float2 v0 = make_float2(f2tf(oacc[nt][0] * inv0), f2tf(oacc[nt][1] * inv0));
        float2 v1 = make_float2(f2tf(oacc[nt][2] * inv1), f2tf(oacc[nt][3] * inv1));
        *(float2*)(O + baseQ + (size_t)(rb + g    ) * C_DIM + c0) = v0;
        *(float2*)(O + baseQ + (size_t)(rb + g + 8) * C_DIM + c0) = v1;
    }
}

// ---------------------------------------------------------------------------
// Launch: round_x, prep_w, gemm q, gemm k, gemm v, flash (launch #6), gemm p
// ---------------------------------------------------------------------------
extern "C" void kernel_launch(void* const* d_in, const int* in_sizes, int n_in,
                              void* d_out, int out_size)
{
    const float* x     = (const float*)d_in[0];
    const float* q_w   = (const float*)d_in[1];
    const float* k_w   = (const float*)d_in[2];
    const float* v_mu  = (const float*)d_in[3];
    const float* v_rho = (const float*)d_in[4];
    const float* v_eps = (const float*)d_in[5];
    const float* p_mu  = (const float*)d_in[6];
    const float* p_rho = (const float*)d_in[7];
    const float* p_eps = (const float*)d_in[8];
    const float* pb_mu = (const float*)d_in[9];
    const float* pb_rho= (const float*)d_in[10];
    const float* pb_eps= (const float*)d_in[11];
    float* out = (float*)d_out;

    float *vw, *pw, *pb, *xr, *qwr, *kwr, *q, *k, *v, *o;
    cudaGetSymbolAddress((void**)&vw,  g_vw);
    cudaGetSymbolAddress((void**)&pw,  g_pw);
    cudaGetSymbolAddress((void**)&pb,  g_pb);
    cudaGetSymbolAddress((void**)&xr,  g_xr);
    cudaGetSymbolAddress((void**)&qwr, g_qwr);
    cudaGetSymbolAddress((void**)&kwr, g_kwr);
    cudaGetSymbolAddress((void**)&q,   g_q);
    cudaGetSymbolAddress((void**)&k,   g_k);
    cudaGetSymbolAddress((void**)&v,   g_v);
    cudaGetSymbolAddress((void**)&o,   g_o);

    cudaFuncSetAttribute(sgemm_tf32,
                         cudaFuncAttributeMaxDynamicSharedMemorySize, GEMM_SMEM);
    cudaFuncSetAttribute(flash_tf32,
                         cudaFuncAttributeMaxDynamicSharedMemorySize, FLASH_SMEM);

    const int nw  = C_DIM * C_DIM;
    const int nx4 = M_DIM * C_DIM / 4;
    const int npw = 4 * nw + C_DIM;

    round_x_kernel<<<(nx4 + 255) / 256, 256>>>(x, xr, nx4);
    prep_w_kernel<<<(npw + 255) / 256, 256>>>(q_w, k_w, v_mu, v_rho, v_eps,
                                              p_mu, p_rho, p_eps,
                                              pb_mu, pb_rho, pb_eps,
                                              qwr, kwr, vw, pw, pb);

    dim3 ggrid(C_DIM / GBN, M_DIM / GBM);
    sgemm_tf32<<<ggrid, 256, GEMM_SMEM>>>(xr, qwr, nullptr, q, C_DIM, C_DIM, 1);
    sgemm_tf32<<<ggrid, 256, GEMM_SMEM>>>(xr, kwr, nullptr, k, C_DIM, C_DIM, 1);
    sgemm_tf32<<<ggrid, 256, GEMM_SMEM>>>(xr, vw,  nullptr, v, C_DIM, C_DIM, 1);

    flash_tf32<<<dim3(SEQ / 64, BATCH * H_DIM), 128, FLASH_SMEM>>>(q, k, v, o);

    sgemm_tf32<<<ggrid, 256, GEMM_SMEM>>>(o, pw, pb, out, C_DIM, C_DIM, 0);
}

// round 8
// speedup vs baseline: 4.9280x; 1.0736x over previous
#include <cuda_runtime.h>
#include <math.h>
#include <stdint.h>

// Problem constants
#define BATCH  4
#define SEQ    2048
#define C_DIM  1024
#define H_DIM  16
#define D_DIM  64
#define M_DIM  (BATCH * SEQ)          // 8192
// softmax scale folded into q weights: D^-0.5 * log2(e)
#define QSCALE (0.125f * 1.4426950408889634f)

// ---------------------------------------------------------------------------
// Device scratch
// ---------------------------------------------------------------------------
__device__ float g_vw [C_DIM * C_DIM];
__device__ float g_pw [C_DIM * C_DIM];
__device__ float g_pb [C_DIM];
__device__ float g_xr [M_DIM * C_DIM];
__device__ float g_qwr[C_DIM * C_DIM];
__device__ float g_kwr[C_DIM * C_DIM];
__device__ float g_q  [M_DIM * C_DIM];
__device__ float g_k  [M_DIM * C_DIM];
__device__ float g_v  [M_DIM * C_DIM];
__device__ float g_o  [M_DIM * C_DIM];

// ---------------------------------------------------------------------------
// Helpers
// ---------------------------------------------------------------------------
__device__ __forceinline__ float f2tf(float x) {
    uint32_t u;
    asm("cvt.rna.tf32.f32 %0, %1;" : "=r"(u) : "f"(x));
    return __uint_as_float(u);
}
__device__ __forceinline__ float4 f2tf4(float4 v) {
    v.x = f2tf(v.x); v.y = f2tf(v.y); v.z = f2tf(v.z); v.w = f2tf(v.w);
    return v;
}
__device__ __forceinline__ float ex2f(float x) {
    float y;
    asm("ex2.approx.f32 %0, %1;" : "=f"(y) : "f"(x));
    return y;
}
__device__ __forceinline__ void mma_tf32(float* d,
                                         uint32_t a0, uint32_t a1, uint32_t a2, uint32_t a3,
                                         uint32_t b0, uint32_t b1)
{
    asm volatile(
        "mma.sync.aligned.m16n8k8.row.col.f32.tf32.tf32.f32 "
        "{%0,%1,%2,%3}, {%4,%5,%6,%7}, {%8,%9}, {%0,%1,%2,%3};\n"
        : "+f"(d[0]), "+f"(d[1]), "+f"(d[2]), "+f"(d[3])
        : "r"(a0), "r"(a1), "r"(a2), "r"(a3), "r"(b0), "r"(b1));
}
__device__ __forceinline__ void ldsm_x4(uint32_t& r0, uint32_t& r1,
                                        uint32_t& r2, uint32_t& r3, uint32_t addr)
{
    asm volatile("ldmatrix.sync.aligned.m8n8.x4.shared.b16 {%0,%1,%2,%3}, [%4];"
                 : "=r"(r0), "=r"(r1), "=r"(r2), "=r"(r3) : "r"(addr));
}
__device__ __forceinline__ uint32_t smem_u32(const void* p) {
    return (uint32_t)__cvta_generic_to_shared(p);
}
__device__ __forceinline__ void cp_async16(void* smem, const void* gmem) {
    uint32_t s = smem_u32(smem);
    asm volatile("cp.async.cg.shared.global [%0], [%1], 16;\n" :: "r"(s), "l"(gmem));
}
__device__ __forceinline__ void cp_commit() {
    asm volatile("cp.async.commit_group;\n");
}
template<int N> __device__ __forceinline__ void cp_wait() {
    asm volatile("cp.async.wait_group %0;\n" :: "n"(N));
}
__device__ __forceinline__ float bayes_w(float mu, float rho, float eps) {
    float sp = (rho > 15.0f) ? rho : log1pf(__expf(rho));
    return fmaf(sp, eps, mu);
}

// ---------------------------------------------------------------------------
// Prep kernels (2 launches so flash is the 6th launch -> ncu captures it)
// ---------------------------------------------------------------------------
__global__ void round_x_kernel(const float* __restrict__ in,
                               float* __restrict__ out, int n4)
{
    int i = blockIdx.x * 256 + threadIdx.x;
    if (i < n4) ((float4*)out)[i] = f2tf4(((const float4*)in)[i]);
}

__global__ void prep_w_kernel(const float* __restrict__ qw,  const float* __restrict__ kw,
                              const float* __restrict__ vmu, const float* __restrict__ vrho,
                              const float* __restrict__ veps,
                              const float* __restrict__ pmu, const float* __restrict__ prho,
                              const float* __restrict__ peps,
                              const float* __restrict__ pbmu, const float* __restrict__ pbrho,
                              const float* __restrict__ pbeps,
                              float* __restrict__ qwr, float* __restrict__ kwr,
                              float* __restrict__ vw,  float* __restrict__ pw,
                              float* __restrict__ pb)
{
    const int nw = C_DIM * C_DIM;
    int i = blockIdx.x * 256 + threadIdx.x;
    if (i < nw) {
        qwr[i] = f2tf(qw[i] * QSCALE);          // softmax scale folded here
    } else if (i < 2 * nw) {
        int j = i - nw;      kwr[j] = f2tf(kw[j]);
    } else if (i < 3 * nw) {
        int j = i - 2 * nw;  vw[j] = f2tf(bayes_w(vmu[j], vrho[j], veps[j]));
    } else if (i < 4 * nw) {
        int j = i - 3 * nw;  pw[j] = f2tf(bayes_w(pmu[j], prho[j], peps[j]));
    } else if (i < 4 * nw + C_DIM) {
        int j = i - 4 * nw;  pb[j] = bayes_w(pbmu[j], pbrho[j], pbeps[j]);
    }
}

// ---------------------------------------------------------------------------
// TF32 SGEMM (NT): 2-stage cp.async + ldmatrix fragment loads.
// 128x128x32 tile, 256 threads = 8 warps (2Mx4N), warp tile 64x32.
// ---------------------------------------------------------------------------
#define GBM 128
#define GBN 128
#define GBK 32
#define GSTR 36
#define GTILE (GBM * GSTR)
#define GEMM_SMEM (4 * GTILE * 4)   // 73728 B

__global__ __launch_bounds__(256, 2)
void sgemm_tf32(const float* __restrict__ A, const float* __restrict__ B,
                const float* __restrict__ bias, float* __restrict__ Cmat,
                int Kdim, int Ndim, int round_out)
{
    extern __shared__ float sm[];
    float* As = sm;                // [2][GTILE]
    float* Bs = sm + 2 * GTILE;    // [2][GTILE]

    const int tid  = threadIdx.x;
    const int lane = tid & 31;
    const int w    = tid >> 5;
    const int wm   = w >> 2;
    const int wn   = w & 3;
    const int g    = lane >> 2;
    const int t    = lane & 3;
    const int m0   = blockIdx.y * GBM;
    const int n0   = blockIdx.x * GBN;

    // ldmatrix per-lane byte offsets (A pattern / B pattern)
    const uint32_t offA = ((lane & 15) * GSTR) * 4 + (lane >> 4) * 16;
    const uint32_t offB = (((lane & 7) + ((lane & 16) >> 1)) * GSTR) * 4 +
                          ((lane >> 3) & 1) * 16;
    const uint32_t uAs = smem_u32(As);
    const uint32_t uBs = smem_u32(Bs);

    float acc[4][4][4];
#pragma unroll
    for (int i = 0; i < 4; i++)
#pragma unroll
        for (int j = 0; j < 4; j++)
#pragma unroll
            for (int c = 0; c < 4; c++) acc[i][j][c] = 0.0f;

    const int lrow = tid >> 3;              // 0..31
    const int lsg  = (tid & 7) * 4;         // 0,4,...,28

    #define LOAD_TILES(st, k0)                                                  \
        do {                                                                    \
            _Pragma("unroll")                                                   \
            for (int it = 0; it < 4; it++) {                                    \
                int row = lrow + it * 32;                                       \
                cp_async16(&As[(st) * GTILE + row * GSTR + lsg],                \
                           A + (size_t)(m0 + row) * Kdim + (k0) + lsg);         \
                cp_async16(&Bs[(st) * GTILE + row * GSTR + lsg],                \
                           B + (size_t)(n0 + row) * Kdim + (k0) + lsg);         \
            }                                                                   \
            cp_commit();                                                        \
        } while (0)

    LOAD_TILES(0, 0);

    int st = 0;
    for (int k0 = 0; k0 < Kdim; k0 += GBK) {
        if (k0 + GBK < Kdim) { LOAD_TILES(st ^ 1, k0 + GBK); cp_wait<1>(); }
        else                 { cp_wait<0>(); }
        __syncthreads();

        const uint32_t aBase = uAs + st * GTILE * 4;
        const uint32_t bBase = uBs + st * GTILE * 4;
#pragma unroll
        for (int kk = 0; kk < 4; kk++) {
            const uint32_t kbB = kk * 32;   // kk*8 floats
            uint32_t af[4][4];
#pragma unroll
            for (int mt = 0; mt < 4; mt++)
                ldsm_x4(af[mt][0], af[mt][1], af[mt][2], af[mt][3],
                        aBase + (uint32_t)(wm * 64 + mt * 16) * GSTR * 4 + offA + kbB);
            uint32_t bf[4][2];
#pragma unroll
            for (int p = 0; p < 2; p++)
                ldsm_x4(bf[2 * p][0], bf[2 * p][1], bf[2 * p + 1][0], bf[2 * p + 1][1],
                        bBase + (uint32_t)(wn * 32 + p * 16) * GSTR * 4 + offB + kbB);
#pragma unroll
            for (int mt = 0; mt < 4; mt++)
#pragma unroll
                for (int nt = 0; nt < 4; nt++)
                    mma_tf32(acc[mt][nt], af[mt][0], af[mt][1], af[mt][2], af[mt][3],
                             bf[nt][0], bf[nt][1]);
        }
        __syncthreads();
        st ^= 1;
    }
    #undef LOAD_TILES

    // Epilogue
#pragma unroll
    for (int mt = 0; mt < 4; mt++) {
        int r0 = m0 + wm * 64 + mt * 16 + g;
#pragma unroll
        for (int nt = 0; nt < 4; nt++) {
            int c0 = n0 + wn * 32 + nt * 8 + 2 * t;
            float bx = 0.0f, by = 0.0f;
            if (bias) { bx = bias[c0]; by = bias[c0 + 1]; }
            float2 v0 = make_float2(acc[mt][nt][0] + bx, acc[mt][nt][1] + by);
            float2 v1 = make_float2(acc[mt][nt][2] + bx, acc[mt][nt][3] + by);
            if (round_out) {
                v0.x = f2tf(v0.x); v0.y = f2tf(v0.y);
                v1.x = f2tf(v1.x); v1.y = f2tf(v1.y);
            }
            *(float2*)(Cmat + (size_t)r0 * Ndim + c0)       = v0;
            *(float2*)(Cmat + (size_t)(r0 + 8) * Ndim + c0) = v1;
        }
    }
}

// ---------------------------------------------------------------------------
// TF32 flash attention, BQ=128: 256 threads = 8 warps, warp owns 16 S-rows.
// cp.async K/V double buffering, Q frags in registers, ldmatrix K/P frags,
// conflict-free V stride, base-2 softmax. BK = 64, D = 64.
// ---------------------------------------------------------------------------
#define FBQ   128
#define FSTR  68                   // K row stride (floats), % 32 banks = 4
#define VSTR  72                   // V row stride, % 32 banks = 8 -> (8t+g) conflict-free
#define KTILE (64 * FSTR)          // 4352 floats
#define VTILE (64 * VSTR)          // 4608 floats
#define PTILE (FBQ * FSTR)         // 8704 floats (P / Q staging)
#define FLASH_SMEM ((2 * KTILE + 2 * VTILE + PTILE) * 4)   // 106496 B

__global__ __launch_bounds__(256, 2)
void flash_tf32(const float* __restrict__ Q, const float* __restrict__ K,
                const float* __restrict__ V, float* __restrict__ O)
{
    extern __shared__ float sm[];
    float* Ks = sm;                          // [2][KTILE]
    float* Vs = sm + 2 * KTILE;              // [2][VTILE]
    float* Ps = sm + 2 * KTILE + 2 * VTILE;  // [PTILE], also Q staging

    const int tid  = threadIdx.x;
    const int lane = tid & 31;
    const int w    = tid >> 5;      // 0..7
    const int g    = lane >> 2;
    const int t    = lane & 3;
    const int rb   = w * 16;        // warp's S-row base (0..112)
    const int bh   = blockIdx.y;
    const int b    = bh >> 4;
    const int h    = bh & 15;
    const int q0   = blockIdx.x * FBQ;

    const size_t baseQ  = ((size_t)b * SEQ + q0) * C_DIM + h * D_DIM;
    const size_t baseKV = ((size_t)b * SEQ) * C_DIM + h * D_DIM;

    // 64-wide rows, 256 threads: 16 threads/row, 16 rows per sweep.
    const int lrow = tid >> 4;            // 0..15
    const int ldq  = (tid & 15) * 4;      // 0,4,...,60

    const uint32_t uKs = smem_u32(Ks);
    const uint32_t uPs = smem_u32(Ps);
    // ldmatrix per-lane byte offsets
    const uint32_t offA = ((lane & 15) * FSTR) * 4 + (lane >> 4) * 16;   // Q/P pattern
    const uint32_t offB = (((lane & 7) + ((lane & 16) >> 1)) * FSTR) * 4 +
                          ((lane >> 3) & 1) * 16;                        // K pattern

    #define LOAD_KV(st, kt)                                                     \
        do {                                                                    \
            _Pragma("unroll")                                                   \
            for (int it = 0; it < 4; it++) {                                    \
                int row = lrow + it * 16;                                       \
                cp_async16(&Ks[(st) * KTILE + row * FSTR + ldq],                \
                           K + baseKV + (size_t)((kt) + row) * C_DIM + ldq);    \
                cp_async16(&Vs[(st) * VTILE + row * VSTR + ldq],                \
                           V + baseKV + (size_t)((kt) + row) * C_DIM + ldq);    \
            }                                                                   \
            cp_commit();                                                        \
        } while (0)

    LOAD_KV(0, 0);

    // Stage Q (pre-rounded, pre-scaled) into Ps: 128 rows, 8 sweeps.
#pragma unroll
    for (int it = 0; it < 8; it++) {
        int row = lrow + it * 16;
        *(float4*)&Ps[row * FSTR + ldq] =
            *(const float4*)(Q + baseQ + (size_t)row * C_DIM + ldq);
    }
    __syncthreads();

    // Hoist this warp's Q fragments (own 16 rows only).
    uint32_t qf[8][4];
#pragma unroll
    for (int kk = 0; kk < 8; kk++)
        ldsm_x4(qf[kk][0], qf[kk][1], qf[kk][2], qf[kk][3],
                uPs + (uint32_t)rb * FSTR * 4 + offA + kk * 32);

    float m0 = -1e30f, m1 = -1e30f, l0 = 0.0f, l1 = 0.0f;
    float oacc[8][4];
#pragma unroll
    for (int nt = 0; nt < 8; nt++)
#pragma unroll
        for (int c = 0; c < 4; c++) oacc[nt][c] = 0.0f;

    int st = 0;
    for (int kt = 0; kt < SEQ; kt += 64) {
        if (kt + 64 < SEQ) { LOAD_KV(st ^ 1, kt + 64); cp_wait<1>(); }
        else               { cp_wait<0>(); }
        __syncthreads();

        const uint32_t kBase = uKs + st * KTILE * 4;
        const float*   Vc    = Vs + st * VTILE;

        // ---- S = Q @ K^T (values already scaled by D^-0.5 * log2e) ----
        float s[8][4];
#pragma unroll
        for (int nt = 0; nt < 8; nt++)
#pragma unroll
            for (int c = 0; c < 4; c++) s[nt][c] = 0.0f;

#pragma unroll
        for (int kk = 0; kk < 8; kk++) {
            const uint32_t kbB = kk * 32;
#pragma unroll
            for (int p = 0; p < 4; p++) {
                uint32_t b0, b1, b2, b3;
                ldsm_x4(b0, b1, b2, b3,
                        kBase + (uint32_t)(p * 16) * FSTR * 4 + offB + kbB);
                mma_tf32(s[2 * p],     qf[kk][0], qf[kk][1], qf[kk][2], qf[kk][3], b0, b1);
                mma_tf32(s[2 * p + 1], qf[kk][0], qf[kk][1], qf[kk][2], qf[kk][3], b2, b3);
            }
        }

        // ---- online softmax (base 2) ----
        float mx0 = -1e30f, mx1 = -1e30f;
#pragma unroll
        for (int nt = 0; nt < 8; nt++) {
            mx0 = fmaxf(mx0, fmaxf(s[nt][0], s[nt][1]));
            mx1 = fmaxf(mx1, fmaxf(s[nt][2], s[nt][3]));
        }
#pragma unroll
        for (int off = 1; off < 4; off <<= 1) {
            mx0 = fmaxf(mx0, __shfl_xor_sync(0xffffffffu, mx0, off));
            mx1 = fmaxf(mx1, __shfl_xor_sync(0xffffffffu, mx1, off));
        }
        float mn0 = fmaxf(m0, mx0), mn1 = fmaxf(m1, mx1);
        float cr0 = ex2f(m0 - mn0), cr1 = ex2f(m1 - mn1);
        float sum0 = 0.0f, sum1 = 0.0f;
#pragma unroll
        for (int nt = 0; nt < 8; nt++) {
            s[nt][0] = ex2f(s[nt][0] - mn0);
            s[nt][1] = ex2f(s[nt][1] - mn0);
            s[nt][2] = ex2f(s[nt][2] - mn1);
            s[nt][3] = ex2f(s[nt][3] - mn1);
            sum0 += s[nt][0] + s[nt][1];
            sum1 += s[nt][2] + s[nt][3];
        }
#pragma unroll
        for (int off = 1; off < 4; off <<= 1) {
            sum0 += __shfl_xor_sync(0xffffffffu, sum0, off);
            sum1 += __shfl_xor_sync(0xffffffffu, sum1, off);
        }
        l0 = l0 * cr0 + sum0;  m0 = mn0;
        l1 = l1 * cr1 + sum1;  m1 = mn1;
#pragma unroll
        for (int nt = 0; nt < 8; nt++) {
            oacc[nt][0] *= cr0; oacc[nt][1] *= cr0;
            oacc[nt][2] *= cr1; oacc[nt][3] *= cr1;
        }

        // ---- stage P (tf32, warp's own rows only) ----
#pragma unroll
        for (int nt = 0; nt < 8; nt++) {
            *(float2*)&Ps[(rb + g    ) * FSTR + nt * 8 + 2 * t] =
                make_float2(f2tf(s[nt][0]), f2tf(s[nt][1]));
            *(float2*)&Ps[(rb + g + 8) * FSTR + nt * 8 + 2 * t] =
                make_float2(f2tf(s[nt][2]), f2tf(s[nt][3]));
        }
        __syncwarp();

        // ---- O += P @ V ----
#pragma unroll
        for (int kk = 0; kk < 8; kk++) {
            const int kb = kk * 8;
            uint32_t a0, a1, a2, a3;
            ldsm_x4(a0, a1, a2, a3,
                    uPs + (uint32_t)rb * FSTR * 4 + offA + kk * 32);
#pragma unroll
            for (int nt = 0; nt < 8; nt++) {
                uint32_t b0 = __float_as_uint(Vc[(kb + t    ) * VSTR + nt * 8 + g]);
                uint32_t b1 = __float_as_uint(Vc[(kb + t + 4) * VSTR + nt * 8 + g]);
                mma_tf32(oacc[nt], a0, a1, a2, a3, b0, b1);
            }
        }
        __syncthreads();
        st ^= 1;
    }
    #undef LOAD_KV

    // ---- normalize + write (rounded: feeds final GEMM) ----
    float inv0 = 1.0f / l0, inv1 = 1.0f / l1;
#pragma unroll
    for (int nt = 0; nt < 8; nt++) {
        int c0 = nt * 8 + 2 * t;
        float2 v0 = make_float2(f2tf(oacc[nt][0] * inv0), f2tf(oacc[nt][1] * inv0));
        float2 v1 = make_float2(f2tf(oacc[nt][2] * inv1), f2tf(oacc[nt][3] * inv1));
        *(float2*)(O + baseQ + (size_t)(rb + g    ) * C_DIM + c0) = v0;
        *(float2*)(O + baseQ + (size_t)(rb + g + 8) * C_DIM + c0) = v1;
    }
}

// ---------------------------------------------------------------------------
// Launch: round_x, prep_w, gemm q, gemm k, gemm v, flash (launch #6), gemm p
// ---------------------------------------------------------------------------
extern "C" void kernel_launch(void* const* d_in, const int* in_sizes, int n_in,
                              void* d_out, int out_size)
{
    const float* x     = (const float*)d_in[0];
    const float* q_w   = (const float*)d_in[1];
    const float* k_w   = (const float*)d_in[2];
    const float* v_mu  = (const float*)d_in[3];
    const float* v_rho = (const float*)d_in[4];
    const float* v_eps = (const float*)d_in[5];
    const float* p_mu  = (const float*)d_in[6];
    const float* p_rho = (const float*)d_in[7];
    const float* p_eps = (const float*)d_in[8];
    const float* pb_mu = (const float*)d_in[9];
    const float* pb_rho= (const float*)d_in[10];
    const float* pb_eps= (const float*)d_in[11];
    float* out = (float*)d_out;

    float *vw, *pw, *pb, *xr, *qwr, *kwr, *q, *k, *v, *o;
    cudaGetSymbolAddress((void**)&vw,  g_vw);
    cudaGetSymbolAddress((void**)&pw,  g_pw);
    cudaGetSymbolAddress((void**)&pb,  g_pb);
    cudaGetSymbolAddress((void**)&xr,  g_xr);
    cudaGetSymbolAddress((void**)&qwr, g_qwr);
    cudaGetSymbolAddress((void**)&kwr, g_kwr);
    cudaGetSymbolAddress((void**)&q,   g_q);
    cudaGetSymbolAddress((void**)&k,   g_k);
    cudaGetSymbolAddress((void**)&v,   g_v);
    cudaGetSymbolAddress((void**)&o,   g_o);

    cudaFuncSetAttribute(sgemm_tf32,
                         cudaFuncAttributeMaxDynamicSharedMemorySize, GEMM_SMEM);
    cudaFuncSetAttribute(flash_tf32,
                         cudaFuncAttributeMaxDynamicSharedMemorySize, FLASH_SMEM);

    const int nw  = C_DIM * C_DIM;
    const int nx4 = M_DIM * C_DIM / 4;
    const int npw = 4 * nw + C_DIM;

    round_x_kernel<<<(nx4 + 255) / 256, 256>>>(x, xr, nx4);
    prep_w_kernel<<<(npw + 255) / 256, 256>>>(q_w, k_w, v_mu, v_rho, v_eps,
                                              p_mu, p_rho, p_eps,
                                              pb_mu, pb_rho, pb_eps,
                                              qwr, kwr, vw, pw, pb);

    dim3 ggrid(C_DIM / GBN, M_DIM / GBM);
    sgemm_tf32<<<ggrid, 256, GEMM_SMEM>>>(xr, qwr, nullptr, q, C_DIM, C_DIM, 1);
    sgemm_tf32<<<ggrid, 256, GEMM_SMEM>>>(xr, kwr, nullptr, k, C_DIM, C_DIM, 1);
    sgemm_tf32<<<ggrid, 256, GEMM_SMEM>>>(xr, vw,  nullptr, v, C_DIM, C_DIM, 1);

    flash_tf32<<<dim3(SEQ / FBQ, BATCH * H_DIM), 256, FLASH_SMEM>>>(q, k, v, o);

    sgemm_tf32<<<ggrid, 256, GEMM_SMEM>>>(o, pw, pb, out, C_DIM, C_DIM, 0);
}